// round 12
// baseline (speedup 1.0000x reference)
#include <cuda_runtime.h>
#include <math.h>
#include <stdint.h>

#define NT 256
#define ROWS 16
#define L 336
#define OFF_MU (1024*96*7)
#define OFF_LV (OFF_MU + 7168*64)
#define OFF_LD (OFF_LV + 7168*64)

// smem pool (floats)
#define P_A     0        // xn[16][336]; aliases: sINP[16][196], r2chunk[16][260], recon[16][100]
#define P_PB    5376
#define P_MEAN  5632
#define P_STD   5648
#define P_SCALE 5664
#define P_B     5680     // ml/r1 out [16][260] = 4160
#define P_WT    9840     // weight tiles: mma 2 x 8 x 520 = 8320 (FFMA uses 2 x 16 x 132 = 4224 subset)
#define SMEM_FLOATS 18160
#define SMEM_BYTES (SMEM_FLOATS*4)

#define PITCH_INP 196    // ≡4 mod 32: conflict-free mma A-frag loads
#define PITCH_B   260    // ≡4 mod 32

// FFMA-path weights, k-major [k][m]
__device__ __align__(16) float g_Wsct[336*128];   // m padded 96->128
__device__ __align__(16) float g_Wmlt[128*128];   // [mu|lv]
__device__ __align__(16) float g_bml[128];
__device__ __align__(16) float g_Wct[16*128];
__device__ __align__(16) float g_bc[128];
// mma-path weights, pre-split tf32 hi/lo planes: [k][hi(M) | lo(M)]
__device__ __align__(16) float g_Wr1t2[192*512];   // M=256
__device__ __align__(16) float g_Wr2t2[256*1024];  // M=512
__device__ __align__(16) float g_Wr3t2[512*256];   // M=128 (m padded 96->128)
__device__ double g_uhat[8*64];
__device__ double g_cflow[8];
__device__ __align__(16) float g_short[7168*96];

__device__ __forceinline__ uint32_t f2tf(float x) {
    uint32_t r; asm("cvt.rna.tf32.f32 %0, %1;" : "=r"(r) : "f"(x)); return r;
}
__device__ __forceinline__ float tf32f(float x) {
    return __uint_as_float(f2tf(x));
}

__global__ void prep_kernel(const float* __restrict__ W_sc,
                            const float* __restrict__ W_mu, const float* __restrict__ b_mu,
                            const float* __restrict__ W_lv, const float* __restrict__ b_lv,
                            const float* __restrict__ W_r3,
                            const float* __restrict__ W_fu, const float* __restrict__ b_fu,
                            const float* __restrict__ W_ts, const float* __restrict__ b_ts,
                            const float* __restrict__ flow_u, const float* __restrict__ flow_w,
                            const float* __restrict__ W_r1, const float* __restrict__ W_r2)
{
    int idx = blockIdx.x * blockDim.x + threadIdx.x;
    int stride = gridDim.x * blockDim.x;
    const int S0 = 336*128;              // Wsct
    const int S1 = S0 + 128*128;         // Wmlt
    const int S2 = S1 + 128;             // bml
    const int S3 = S2 + 16*128;          // Wct
    const int S4 = S3 + 128;             // bc
    const int S5 = S4 + 192*512;         // Wr1t2
    const int S6 = S5 + 256*1024;        // Wr2t2
    const int S7 = S6 + 512*256;         // Wr3t2
    const int S8 = S7 + 8;               // flows
    for (int i = idx; i < S8; i += stride) {
        if (i < S0) {
            int k = i >> 7, m = i & 127;
            g_Wsct[i] = (m < 96) ? W_sc[m*336 + k] : 0.f;
        } else if (i < S1) {
            int j = i - S0;
            int k = j >> 7, m = j & 127;
            g_Wmlt[j] = (m < 64) ? W_mu[m*128 + k] : W_lv[(m-64)*128 + k];
        } else if (i < S2) {
            int j = i - S1;
            g_bml[j] = (j < 64) ? b_mu[j] : b_lv[j-64];
        } else if (i < S3) {
            int j = i - S2;
            int l = j >> 7, h = j & 127;
            float s = 0.f;
            for (int d = 0; d < 128; d++) s += W_fu[h*256 + d] * W_ts[d*16 + l];
            g_Wct[j] = s;
        } else if (i < S4) {
            int h = i - S3;
            float s = 0.f;
            for (int d = 0; d < 128; d++) s += W_fu[h*256 + d] * b_ts[d];
            g_bc[h] = s + b_fu[h];
        } else if (i < S5) {
            int j = i - S4;
            int k = j >> 9, c = j & 511;
            int m = c & 255, plane = c >> 8;
            float w = W_r1[m*192 + k];
            float hi = tf32f(w);
            g_Wr1t2[j] = plane ? tf32f(w - hi) : hi;
        } else if (i < S6) {
            int j = i - S5;
            int k = j >> 10, c = j & 1023;
            int m = c & 511, plane = c >> 9;
            float w = W_r2[m*256 + k];
            float hi = tf32f(w);
            g_Wr2t2[j] = plane ? tf32f(w - hi) : hi;
        } else if (i < S7) {
            int j = i - S6;
            int k = j >> 8, c = j & 255;
            int m = c & 127, plane = c >> 7;
            float w = (m < 96) ? W_r3[m*512 + k] : 0.f;
            float hi = tf32f(w);
            g_Wr3t2[j] = plane ? tf32f(w - hi) : hi;
        } else {
            int fi = i - S7;
            double s = 0.0, wsq = 0.0;
            for (int d = 0; d < 64; d++) {
                double u = (double)flow_u[fi*64+d], w = (double)flow_w[fi*64+d];
                s += u*w; wsq += w*w;
            }
            double sp = (s > 0.0) ? s + log1p(exp(-s)) : log1p(exp(s));
            double m = -1.0 + sp;
            double coef = m / (wsq + 1e-6);
            for (int d = 0; d < 64; d++)
                g_uhat[fi*64+d] = (double)flow_u[fi*64+d] + coef*(double)flow_w[fi*64+d];
            g_cflow[fi] = s + coef * wsq;
        }
    }
}

__device__ __forceinline__ float gelu_f(float x) {
    return 0.5f * x * (1.f + erff(x * 0.70710678118654752f));
}
__device__ __forceinline__ uint32_t smem_u32(const void* p) {
    return (uint32_t)__cvta_generic_to_shared(p);
}
#define CP_ASYNC16(d, s) asm volatile("cp.async.ca.shared.global [%0], [%1], 16;\n" :: "r"(d), "l"(s))
#define CP_COMMIT()      asm volatile("cp.async.commit_group;\n" ::: "memory")
#define CP_WAIT0()       asm volatile("cp.async.wait_group 0;\n" ::: "memory")

#define MMA_TF32(c, a0,a1,a2,a3, b0,b1) \
    asm volatile("mma.sync.aligned.m16n8k8.row.col.f32.tf32.tf32.f32 " \
        "{%0,%1,%2,%3}, {%4,%5,%6,%7}, {%8,%9}, {%0,%1,%2,%3};" \
        : "+f"((c)[0]), "+f"((c)[1]), "+f"((c)[2]), "+f"((c)[3]) \
        : "r"(a0), "r"(a1), "r"(a2), "r"(a3), "r"(b0), "r"(b1))

// ---------------- FFMA fp32 GEMM (bit-exact path; unchanged from R7) ----------------
__device__ __forceinline__ void gemm_s(
    const float* smIn, int pitch, int K,
    const float* __restrict__ Wk, const float* __restrict__ bias,
    int Mreal, float* smOut, int opitch, int act, float* Wt,
    float* acc, int init, int fin)
{
    const int tid = threadIdx.x;
    const int rg = tid >> 6;
    const int mloc = (tid & 63) << 1;
    const int srow = tid >> 5;
    const int scol = (tid & 31) << 2;
    const float* in0 = smIn + rg*4*pitch;
    const int T = K >> 4;
    {
        #pragma unroll
        for (int s2 = 0; s2 < 2; s2++) {
            uint32_t d = smem_u32(Wt + (srow + 8*s2)*132 + scol);
            CP_ASYNC16(d, Wk + (size_t)(srow + 8*s2)*128 + scol);
        }
        CP_COMMIT();
    }
    if (init) {
        #pragma unroll
        for (int i = 0; i < 8; i++) acc[i] = 0.f;
    }
    int buf = 0;
    for (int t = 0; t < T; t++) {
        CP_WAIT0();
        __syncthreads();
        if (t + 1 < T) {
            const float* g = Wk + (size_t)((t+1)*16)*128;
            float* Wd = Wt + (buf^1)*2112;
            #pragma unroll
            for (int s2 = 0; s2 < 2; s2++) {
                uint32_t d = smem_u32(Wd + (srow + 8*s2)*132 + scol);
                CP_ASYNC16(d, g + (size_t)(srow + 8*s2)*128 + scol);
            }
            CP_COMMIT();
        }
        const float* W = Wt + buf*2112;
        const float* i0 = in0 + t*16;
        #pragma unroll
        for (int kk = 0; kk < 16; kk += 2) {
            float2 w0 = *(const float2*)&W[kk*132 + mloc];
            float2 w1 = *(const float2*)&W[(kk+1)*132 + mloc];
            float2 x0 = *(const float2*)(i0 + kk);
            float2 x1 = *(const float2*)(i0 + pitch + kk);
            float2 x2 = *(const float2*)(i0 + 2*pitch + kk);
            float2 x3 = *(const float2*)(i0 + 3*pitch + kk);
            acc[0] = fmaf(x0.x, w0.x, acc[0]); acc[0] = fmaf(x0.y, w1.x, acc[0]);
            acc[1] = fmaf(x0.x, w0.y, acc[1]); acc[1] = fmaf(x0.y, w1.y, acc[1]);
            acc[2] = fmaf(x1.x, w0.x, acc[2]); acc[2] = fmaf(x1.y, w1.x, acc[2]);
            acc[3] = fmaf(x1.x, w0.y, acc[3]); acc[3] = fmaf(x1.y, w1.y, acc[3]);
            acc[4] = fmaf(x2.x, w0.x, acc[4]); acc[4] = fmaf(x2.y, w1.x, acc[4]);
            acc[5] = fmaf(x2.x, w0.y, acc[5]); acc[5] = fmaf(x2.y, w1.y, acc[5]);
            acc[6] = fmaf(x3.x, w0.x, acc[6]); acc[6] = fmaf(x3.y, w1.x, acc[6]);
            acc[7] = fmaf(x3.x, w0.y, acc[7]); acc[7] = fmaf(x3.y, w1.y, acc[7]);
        }
        buf ^= 1;
    }
    __syncthreads();
    if (fin && mloc < Mreal) {
        float b0 = bias[mloc], b1 = bias[mloc+1];
        int r0 = rg*4;
        #pragma unroll
        for (int r = 0; r < 4; r++) {
            float2 o;
            o.x = acc[2*r]   + b0;
            o.y = acc[2*r+1] + b1;
            if (act) { o.x = gelu_f(o.x); o.y = gelu_f(o.y); }
            *(float2*)&smOut[(size_t)(r0+r)*opitch + mloc] = o;
        }
    }
}

// ---------------- 3xTF32 tensor-core GEMM, pre-split weights ----------------
// OUT[16 x M] (+)= IN[16 x K] @ W. W in gmem as [k][hi(Mfull)|...|lo at +gap], row stride wstride.
// M = 64*NTILES. KT=8 (one k8/tile). Smem tile row: [hi(M) pad | lo(M)] pitch TRP (≡8 mod 32).
// B-frags loaded pre-split (zero ALU); A split hi/lo at runtime. 3 mma per n-tile per tile.
template<int NTILES>
__device__ __forceinline__ void gemm_mma(
    const float* smIn, int pitch, int K,
    const float* __restrict__ Wk, int wstride, int gap,
    const float* __restrict__ bias,
    float* smOut, int opitch, int act, float* Wt,
    float* C, int init, int fin, int nws)
{
    constexpr int MW  = 64*NTILES;          // hi-plane width
    constexpr int LO  = MW + 8;             // lo-plane smem offset
    constexpr int TRP = 2*MW + 8;           // tile row pitch (520 / 264)
    constexpr int BUF = 8*TRP;
    constexpr int CPR = (2*MW) >> 2;        // 16B chunks per row (128 / 64)
    constexpr int SITER = (8*CPR) / 256;    // staging iters (4 / 2)
    const int tid = threadIdx.x;
    const int lane = tid & 31;
    const int warp = tid >> 5;
    const int g = lane >> 2, t4 = lane & 3;
    const int n0w = warp * (8*NTILES);
    const int T = K >> 3;
    {
        #pragma unroll
        for (int s = 0; s < SITER; s++) {
            int idx = s*256 + tid;
            int row = idx / CPR, cc = idx % CPR;
            int colf = cc << 2;
            int dcol = (colf < MW) ? colf : LO + (colf - MW);
            int scolf = (colf < MW) ? colf : gap + (colf - MW);
            uint32_t d = smem_u32(Wt + row*TRP + dcol);
            CP_ASYNC16(d, Wk + (size_t)row*wstride + scolf);
        }
        CP_COMMIT();
    }
    if (init) {
        #pragma unroll
        for (int i = 0; i < 4*NTILES; i++) C[i] = 0.f;
    }
    int buf = 0;
    for (int t = 0; t < T; t++) {
        CP_WAIT0();
        __syncthreads();
        if (t + 1 < T) {
            const float* gsrc = Wk + (size_t)((t+1)*8)*wstride;
            float* Wd = Wt + (buf^1)*BUF;
            #pragma unroll
            for (int s = 0; s < SITER; s++) {
                int idx = s*256 + tid;
                int row = idx / CPR, cc = idx % CPR;
                int colf = cc << 2;
                int dcol = (colf < MW) ? colf : LO + (colf - MW);
                int scolf = (colf < MW) ? colf : gap + (colf - MW);
                uint32_t d = smem_u32(Wd + row*TRP + dcol);
                CP_ASYNC16(d, gsrc + (size_t)row*wstride + scolf);
            }
            CP_COMMIT();
        }
        const float* W = Wt + buf*BUF;
        const float* ia = smIn + t*8;
        float ar0 = ia[g*pitch + t4];
        float ar1 = ia[(g+8)*pitch + t4];
        float ar2 = ia[g*pitch + t4 + 4];
        float ar3 = ia[(g+8)*pitch + t4 + 4];
        uint32_t ah0 = f2tf(ar0), ah1 = f2tf(ar1), ah2 = f2tf(ar2), ah3 = f2tf(ar3);
        uint32_t al0 = f2tf(ar0 - __uint_as_float(ah0));
        uint32_t al1 = f2tf(ar1 - __uint_as_float(ah1));
        uint32_t al2 = f2tf(ar2 - __uint_as_float(ah2));
        uint32_t al3 = f2tf(ar3 - __uint_as_float(ah3));
        #pragma unroll
        for (int nt = 0; nt < NTILES; nt++) {
            int n = n0w + nt*8 + g;
            uint32_t bh0 = __float_as_uint(W[t4*TRP + n]);
            uint32_t bh1 = __float_as_uint(W[(t4+4)*TRP + n]);
            uint32_t bl0 = __float_as_uint(W[t4*TRP + LO + n]);
            uint32_t bl1 = __float_as_uint(W[(t4+4)*TRP + LO + n]);
            float* c = C + nt*4;
            MMA_TF32(c, ah0, ah1, ah2, ah3, bh0, bh1);
            MMA_TF32(c, ah0, ah1, ah2, ah3, bl0, bl1);
            MMA_TF32(c, al0, al1, al2, al3, bh0, bh1);
        }
        buf ^= 1;
    }
    __syncthreads();
    if (fin && warp < nws) {
        #pragma unroll
        for (int nt = 0; nt < NTILES; nt++) {
            int col = n0w + nt*8 + 2*t4;
            float2 bb = *(const float2*)&bias[col];
            float2 o;
            o.x = C[nt*4+0] + bb.x; o.y = C[nt*4+1] + bb.y;
            if (act) { o.x = gelu_f(o.x); o.y = gelu_f(o.y); }
            *(float2*)&smOut[(size_t)g*opitch + col] = o;
            o.x = C[nt*4+2] + bb.x; o.y = C[nt*4+3] + bb.y;
            if (act) { o.x = gelu_f(o.x); o.y = gelu_f(o.y); }
            *(float2*)&smOut[(size_t)(g+8)*opitch + col] = o;
        }
    }
}

__global__ void __launch_bounds__(NT, 3) fused_kernel(
    const float* __restrict__ x_enc, const float* __restrict__ eps,
    const float* __restrict__ p_aw, const float* __restrict__ p_ab,
    const float* __restrict__ b_sc,
    const float* __restrict__ b_r1, const float* __restrict__ b_r2,
    const float* __restrict__ b_r3,
    const float* __restrict__ flow_w, const float* __restrict__ flow_b,
    float* __restrict__ out)
{
    extern __shared__ float smn[];
    float* sA    = smn + P_A;
    float* sINP  = smn + P_A;
    float* sPB   = smn + P_PB;
    float* sMean = smn + P_MEAN;
    float* sStd  = smn + P_STD;
    float* sScale= smn + P_SCALE;
    float* sB    = smn + P_B;
    float* sWT   = smn + P_WT;

    int tid = threadIdx.x;
    int n0 = blockIdx.x * ROWS;
    float aw = p_aw[0], ab = p_ab[0];
    int warp = tid >> 5, lane = tid & 31;
    float acc[8];

    // ---- 1. load x ----
    for (int t = tid; t < ROWS*L; t += NT) {
        int r = t & 15, l = t >> 4;
        int n = n0 + r;
        int b = n / 7, c = n - b*7;
        sA[r*L + l] = x_enc[(b*L + l)*7 + c];
    }
    __syncthreads();

    // ---- 2. per-row mean/std ----
    #pragma unroll
    for (int rr = 0; rr < 2; rr++) {
        int r = warp*2 + rr;
        const float* row = sA + r*L;
        float s = 0.f, sq = 0.f;
        for (int l2 = lane; l2 < L; l2 += 32) { float v = row[l2]; s += v; sq += v*v; }
        #pragma unroll
        for (int o = 16; o > 0; o >>= 1) {
            s  += __shfl_xor_sync(0xffffffffu, s, o);
            sq += __shfl_xor_sync(0xffffffffu, sq, o);
        }
        if (lane == 0) {
            float mean = s * (1.f/336.f);
            float var = sq * (1.f/336.f) - mean*mean;
            float sd = sqrtf(var + 1e-5f);
            sMean[r] = mean; sStd[r] = sd; sScale[r] = aw / sd;
        }
    }
    __syncthreads();

    // ---- 3. normalize ----
    for (int t = tid; t < ROWS*L; t += NT) {
        int r = t / L;
        sA[t] = (sA[t] - sMean[r]) * sScale[r] + ab;
    }
    __syncthreads();

    // ---- 4. pbar ----
    {
        int r = tid >> 4, j = tid & 15;
        float s = 0.f;
        #pragma unroll
        for (int pp = 0; pp < 41; pp++) s += sA[r*L + pp*8 + j];
        sPB[r*16 + j] = s * (1.f/41.f);
    }

    // ---- 5. shortcut (FFMA exact) -> gmem scratch ----
    gemm_s(sA, L, L, g_Wsct, b_sc, 96, g_short + (size_t)n0*96, 96, 0, sWT, acc, 1, 1);
    // ---- 6. h (FFMA exact) -> sINP[:,64:192] ----
    gemm_s(sPB, 16, 16, g_Wct, g_bc, 128, sINP + 64, PITCH_INP, 0, sWT, acc, 1, 1);
    // ---- 7. [mu|lv] (FFMA exact) -> sB ----
    gemm_s(sINP + 64, PITCH_INP, 128, g_Wmlt, g_bml, 128, sB, PITCH_B, 0, sWT, acc, 1, 1);
    __syncthreads();

    // ---- 8+9. reparam + flows (FP64, bit-identical) ----
    #pragma unroll
    for (int rr = 0; rr < 2; rr++) {
        int r = warp + rr*8;
        int n = n0 + r;
        float mu0 = sB[r*PITCH_B + lane];
        float mu1 = sB[r*PITCH_B + 32 + lane];
        float lv0 = sB[r*PITCH_B + 64 + lane];
        float lv1 = sB[r*PITCH_B + 96 + lane];
        out[OFF_MU + n*64 + lane]      = mu0;
        out[OFF_MU + n*64 + 32 + lane] = mu1;
        out[OFF_LV + n*64 + lane]      = lv0;
        out[OFF_LV + n*64 + 32 + lane] = lv1;
        double z0 = (double)mu0 + (double)eps[n*64 + lane]      * exp(0.5 * (double)lv0);
        double z1 = (double)mu1 + (double)eps[n*64 + 32 + lane] * exp(0.5 * (double)lv1);
        double ld = 0.0;
        #pragma unroll
        for (int i = 0; i < 8; i++) {
            double w0 = (double)flow_w[i*64 + lane];
            double w1 = (double)flow_w[i*64 + 32 + lane];
            double dot = z0*w0 + z1*w1;
            #pragma unroll
            for (int o = 16; o > 0; o >>= 1) dot += __shfl_xor_sync(0xffffffffu, dot, o);
            double th = tanh(dot + (double)flow_b[i]);
            z0 += th * g_uhat[i*64 + lane];
            z1 += th * g_uhat[i*64 + 32 + lane];
            ld += log(fabs(1.0 + (1.0 - th*th) * g_cflow[i]) + 1e-6);
        }
        sINP[r*PITCH_INP + lane]      = (float)z0;
        sINP[r*PITCH_INP + 32 + lane] = (float)z1;
        if (lane == 0) out[OFF_LD + n] = (float)ld;
    }

    // ---- 10. r1 (3xTF32 mma, pre-split W) -> sB ----
    {
        float C1[16];
        gemm_mma<4>(sINP, PITCH_INP, 192, g_Wr1t2, 512, 256, b_r1, sB, PITCH_B, 1, sWT, C1, 1, 1, 8);
    }
    // ---- 11+12. r2 chunks (mma) fused with r3 accumulation (mma, C persists) ----
    {
        float C3[8];
        #pragma unroll
        for (int c = 0; c < 2; c++) {
            float C2[16];
            gemm_mma<4>(sB, PITCH_B, 256, g_Wr2t2 + 256*c, 1024, 512, b_r2 + 256*c,
                        sA, PITCH_B, 1, sWT, C2, 1, 1, 8);
            gemm_mma<2>(sA, PITCH_B, 256, g_Wr3t2 + (size_t)(256*c)*256, 256, 128, b_r3,
                        sA, 100, 0, sWT, C3, c == 0, c == 1, 6);
        }
    }
    __syncthreads();

    // ---- 13. denorm + scatter (recon in sA pitch 100) ----
    float inv_aw = 1.f / (aw + 1e-10f);
    for (int t = tid; t < ROWS*96; t += NT) {
        int r = t & 15, pcol = t >> 4;
        int n = n0 + r;
        float v = sA[r*100 + pcol] + g_short[(size_t)n*96 + pcol];
        float den = fmaf((v - ab) * inv_aw, sStd[r], sMean[r]);
        int b = n/7, c = n - b*7;
        out[(b*96 + pcol)*7 + c] = den;
    }
}

extern "C" void kernel_launch(void* const* d_in, const int* in_sizes, int n_in,
                              void* d_out, int out_size) {
    const float* x_enc  = (const float*)d_in[0];
    const float* eps    = (const float*)d_in[1];
    const float* aw     = (const float*)d_in[2];
    const float* ab     = (const float*)d_in[3];
    const float* W_sc   = (const float*)d_in[4];
    const float* b_sc   = (const float*)d_in[5];
    const float* W_ts   = (const float*)d_in[6];
    const float* b_ts   = (const float*)d_in[7];
    const float* W_fu   = (const float*)d_in[8];
    const float* b_fu   = (const float*)d_in[9];
    const float* W_mu   = (const float*)d_in[10];
    const float* b_mu   = (const float*)d_in[11];
    const float* W_lv   = (const float*)d_in[12];
    const float* b_lv   = (const float*)d_in[13];
    const float* flow_u = (const float*)d_in[14];
    const float* flow_w = (const float*)d_in[15];
    const float* flow_b = (const float*)d_in[16];
    const float* W_r1   = (const float*)d_in[17];
    const float* b_r1   = (const float*)d_in[18];
    const float* W_r2   = (const float*)d_in[19];
    const float* b_r2   = (const float*)d_in[20];
    const float* W_r3   = (const float*)d_in[21];
    const float* b_r3   = (const float*)d_in[22];
    float* out = (float*)d_out;

    cudaFuncSetAttribute(fused_kernel, cudaFuncAttributeMaxDynamicSharedMemorySize, SMEM_BYTES);

    prep_kernel<<<128, 256>>>(W_sc, W_mu, b_mu, W_lv, b_lv, W_r3,
                              W_fu, b_fu, W_ts, b_ts, flow_u, flow_w, W_r1, W_r2);
    fused_kernel<<<448, NT, SMEM_BYTES>>>(x_enc, eps, aw, ab, b_sc,
                                          b_r1, b_r2, b_r3,
                                          flow_w, flow_b, out);
}

// round 13
// speedup vs baseline: 1.0577x; 1.0577x over previous
#include <cuda_runtime.h>
#include <math.h>
#include <stdint.h>

#define NT 256
#define ROWS 16
#define L 336
#define OFF_MU (1024*96*7)
#define OFF_LV (OFF_MU + 7168*64)
#define OFF_LD (OFF_LV + 7168*64)

// smem pool (floats)
#define P_A     0        // xn[16][336]; aliases: sINP[16][196], r2chunk[16][260], recon[16][100]
#define P_PB    5376
#define P_MEAN  5632
#define P_STD   5648
#define P_SCALE 5664
#define P_B     5680     // ml/r1 out [16][260] = 4160
#define P_WT    9840     // gemm_s shared tiles (max 2x32x132=8448) / mma per-warp slices (8x1152=9216)
#define SMEM_FLOATS 19056
#define SMEM_BYTES (SMEM_FLOATS*4)

#define PITCH_INP 196    // ≡4 mod 32
#define PITCH_B   260    // ≡4 mod 32

// FFMA-path weights, k-major [k][m]
__device__ __align__(16) float g_Wsct[336*128];   // m padded 96->128
__device__ __align__(16) float g_Wmlt[128*128];   // [mu|lv]
__device__ __align__(16) float g_bml[128];
__device__ __align__(16) float g_Wct[16*128];
__device__ __align__(16) float g_bc[128];
// mma-path weights, pre-split tf32 hi/lo planes: [k][hi(M) | lo(M)]
__device__ __align__(16) float g_Wr1t2[192*512];   // M=256
__device__ __align__(16) float g_Wr2t2[256*1024];  // M=512
__device__ __align__(16) float g_Wr3t2[512*256];   // M=128 (m padded 96->128)
__device__ double g_uhat[8*64];
__device__ double g_cflow[8];
__device__ __align__(16) float g_short[7168*96];

__device__ __forceinline__ uint32_t f2tf(float x) {
    uint32_t r; asm("cvt.rna.tf32.f32 %0, %1;" : "=r"(r) : "f"(x)); return r;
}
__device__ __forceinline__ float tf32f(float x) {
    return __uint_as_float(f2tf(x));
}

__global__ void prep_kernel(const float* __restrict__ W_sc,
                            const float* __restrict__ W_mu, const float* __restrict__ b_mu,
                            const float* __restrict__ W_lv, const float* __restrict__ b_lv,
                            const float* __restrict__ W_r3,
                            const float* __restrict__ W_fu, const float* __restrict__ b_fu,
                            const float* __restrict__ W_ts, const float* __restrict__ b_ts,
                            const float* __restrict__ flow_u, const float* __restrict__ flow_w,
                            const float* __restrict__ W_r1, const float* __restrict__ W_r2)
{
    int idx = blockIdx.x * blockDim.x + threadIdx.x;
    int stride = gridDim.x * blockDim.x;
    const int S0 = 336*128;
    const int S1 = S0 + 128*128;
    const int S2 = S1 + 128;
    const int S3 = S2 + 16*128;
    const int S4 = S3 + 128;
    const int S5 = S4 + 192*512;
    const int S6 = S5 + 256*1024;
    const int S7 = S6 + 512*256;
    const int S8 = S7 + 8;
    for (int i = idx; i < S8; i += stride) {
        if (i < S0) {
            int k = i >> 7, m = i & 127;
            g_Wsct[i] = (m < 96) ? W_sc[m*336 + k] : 0.f;
        } else if (i < S1) {
            int j = i - S0;
            int k = j >> 7, m = j & 127;
            g_Wmlt[j] = (m < 64) ? W_mu[m*128 + k] : W_lv[(m-64)*128 + k];
        } else if (i < S2) {
            int j = i - S1;
            g_bml[j] = (j < 64) ? b_mu[j] : b_lv[j-64];
        } else if (i < S3) {
            int j = i - S2;
            int l = j >> 7, h = j & 127;
            float s = 0.f;
            for (int d = 0; d < 128; d++) s += W_fu[h*256 + d] * W_ts[d*16 + l];
            g_Wct[j] = s;
        } else if (i < S4) {
            int h = i - S3;
            float s = 0.f;
            for (int d = 0; d < 128; d++) s += W_fu[h*256 + d] * b_ts[d];
            g_bc[h] = s + b_fu[h];
        } else if (i < S5) {
            int j = i - S4;
            int k = j >> 9, c = j & 511;
            int m = c & 255, plane = c >> 8;
            float w = W_r1[m*192 + k];
            float hi = tf32f(w);
            g_Wr1t2[j] = plane ? tf32f(w - hi) : hi;
        } else if (i < S6) {
            int j = i - S5;
            int k = j >> 10, c = j & 1023;
            int m = c & 511, plane = c >> 9;
            float w = W_r2[m*256 + k];
            float hi = tf32f(w);
            g_Wr2t2[j] = plane ? tf32f(w - hi) : hi;
        } else if (i < S7) {
            int j = i - S6;
            int k = j >> 8, c = j & 255;
            int m = c & 127, plane = c >> 7;
            float w = (m < 96) ? W_r3[m*512 + k] : 0.f;
            float hi = tf32f(w);
            g_Wr3t2[j] = plane ? tf32f(w - hi) : hi;
        } else {
            int fi = i - S7;
            double s = 0.0, wsq = 0.0;
            for (int d = 0; d < 64; d++) {
                double u = (double)flow_u[fi*64+d], w = (double)flow_w[fi*64+d];
                s += u*w; wsq += w*w;
            }
            double sp = (s > 0.0) ? s + log1p(exp(-s)) : log1p(exp(s));
            double m = -1.0 + sp;
            double coef = m / (wsq + 1e-6);
            for (int d = 0; d < 64; d++)
                g_uhat[fi*64+d] = (double)flow_u[fi*64+d] + coef*(double)flow_w[fi*64+d];
            g_cflow[fi] = s + coef * wsq;
        }
    }
}

__device__ __forceinline__ float gelu_f(float x) {
    return 0.5f * x * (1.f + erff(x * 0.70710678118654752f));
}
__device__ __forceinline__ uint32_t smem_u32(const void* p) {
    return (uint32_t)__cvta_generic_to_shared(p);
}
#define CP_ASYNC16(d, s) asm volatile("cp.async.ca.shared.global [%0], [%1], 16;\n" :: "r"(d), "l"(s))
#define CP_COMMIT()      asm volatile("cp.async.commit_group;\n" ::: "memory")
#define CP_WAIT0()       asm volatile("cp.async.wait_group 0;\n" ::: "memory")

#define MMA_TF32(c, a0,a1,a2,a3, b0,b1) \
    asm volatile("mma.sync.aligned.m16n8k8.row.col.f32.tf32.tf32.f32 " \
        "{%0,%1,%2,%3}, {%4,%5,%6,%7}, {%8,%9}, {%0,%1,%2,%3};" \
        : "+f"((c)[0]), "+f"((c)[1]), "+f"((c)[2]), "+f"((c)[3]) \
        : "r"(a0), "r"(a1), "r"(a2), "r"(a3), "r"(b0), "r"(b1))

// ---------------- FFMA fp32 GEMM (bit-exact path), templated k-tile depth ----------------
// One block barrier per tile; KT in {16,24,32}, K % KT == 0.
template<int KT>
__device__ __forceinline__ void gemm_s(
    const float* smIn, int pitch, int K,
    const float* __restrict__ Wk, const float* __restrict__ bias,
    int Mreal, float* smOut, int opitch, int act, float* Wt,
    float* acc, int init, int fin)
{
    constexpr int BUFS = KT*132;
    constexpr int SIT  = KT/8;      // (KT*32 chunks)/256 threads
    const int tid = threadIdx.x;
    const int rg = tid >> 6;
    const int mloc = (tid & 63) << 1;
    const float* in0 = smIn + rg*4*pitch;
    const int T = K / KT;
    {
        #pragma unroll
        for (int s = 0; s < SIT; s++) {
            int idx = s*256 + tid;
            int row = idx >> 5, col = (idx & 31) << 2;
            CP_ASYNC16(smem_u32(Wt + row*132 + col), Wk + (size_t)row*128 + col);
        }
        CP_COMMIT();
    }
    if (init) {
        #pragma unroll
        for (int i = 0; i < 8; i++) acc[i] = 0.f;
    }
    int buf = 0;
    for (int t = 0; t < T; t++) {
        CP_WAIT0();
        __syncthreads();            // tile t visible; tile t-1 consumers done
        if (t + 1 < T) {
            const float* g = Wk + (size_t)((t+1)*KT)*128;
            float* Wd = Wt + (buf^1)*BUFS;
            #pragma unroll
            for (int s = 0; s < SIT; s++) {
                int idx = s*256 + tid;
                int row = idx >> 5, col = (idx & 31) << 2;
                CP_ASYNC16(smem_u32(Wd + row*132 + col), g + (size_t)row*128 + col);
            }
            CP_COMMIT();
        }
        const float* W = Wt + buf*BUFS;
        const float* i0 = in0 + t*KT;
        #pragma unroll
        for (int kk = 0; kk < KT; kk += 2) {
            float2 w0 = *(const float2*)&W[kk*132 + mloc];
            float2 w1 = *(const float2*)&W[(kk+1)*132 + mloc];
            float2 x0 = *(const float2*)(i0 + kk);
            float2 x1 = *(const float2*)(i0 + pitch + kk);
            float2 x2 = *(const float2*)(i0 + 2*pitch + kk);
            float2 x3 = *(const float2*)(i0 + 3*pitch + kk);
            acc[0] = fmaf(x0.x, w0.x, acc[0]); acc[0] = fmaf(x0.y, w1.x, acc[0]);
            acc[1] = fmaf(x0.x, w0.y, acc[1]); acc[1] = fmaf(x0.y, w1.y, acc[1]);
            acc[2] = fmaf(x1.x, w0.x, acc[2]); acc[2] = fmaf(x1.y, w1.x, acc[2]);
            acc[3] = fmaf(x1.x, w0.y, acc[3]); acc[3] = fmaf(x1.y, w1.y, acc[3]);
            acc[4] = fmaf(x2.x, w0.x, acc[4]); acc[4] = fmaf(x2.y, w1.x, acc[4]);
            acc[5] = fmaf(x2.x, w0.y, acc[5]); acc[5] = fmaf(x2.y, w1.y, acc[5]);
            acc[6] = fmaf(x3.x, w0.x, acc[6]); acc[6] = fmaf(x3.y, w1.x, acc[6]);
            acc[7] = fmaf(x3.x, w0.y, acc[7]); acc[7] = fmaf(x3.y, w1.y, acc[7]);
        }
        buf ^= 1;
    }
    __syncthreads();
    if (fin && mloc < Mreal) {
        float b0 = bias[mloc], b1 = bias[mloc+1];
        int r0 = rg*4;
        #pragma unroll
        for (int r = 0; r < 4; r++) {
            float2 o;
            o.x = acc[2*r]   + b0;
            o.y = acc[2*r+1] + b1;
            if (act) { o.x = gelu_f(o.x); o.y = gelu_f(o.y); }
            *(float2*)&smOut[(size_t)(r0+r)*opitch + mloc] = o;
        }
    }
}

// ---------------- 3xTF32 mma GEMM, warp-private barrier-free pipeline ----------------
// Each warp stages ONLY its own 8*NTILES-column slice (hi+lo planes) into a private
// smem slice; sync = cp.async.wait_group + __syncwarp. NO block barriers in mainloop.
// Entry __syncthreads protects smIn; optional pre-store __syncthreads when fin.
// WtW = per-warp slice base (stride 1152 floats; 2 buffers).
template<int NTILES>
__device__ __forceinline__ void gemm_mma(
    const float* smIn, int pitch, int K,
    const float* __restrict__ Wk, int wstride, int gap,
    const float* __restrict__ bias,
    float* smOut, int opitch, int act, float* WtW,
    float* C, int init, int fin, int nws)
{
    constexpr int PW    = (NTILES == 4) ? 72 : 40;   // slice pitch (t4*PW mod 32 = t4*8: conflict-free)
    constexpr int LOFF  = (NTILES == 4) ? 36 : 20;   // lo-plane offset within row
    constexpr int SLICE = 8*PW;
    constexpr int CPR2  = 4*NTILES;                  // 16B chunks per k-row (hi+lo)
    constexpr int SIT   = NTILES;                    // (8*CPR2)/32 lanes
    const int tid = threadIdx.x;
    const int lane = tid & 31;
    const int warp = tid >> 5;
    const int g = lane >> 2, t4 = lane & 3;
    const int n0w = warp * (8*NTILES);
    const int T = K >> 3;
    __syncthreads();                                 // smIn ready; prior slice reads retired
    {
        #pragma unroll
        for (int s = 0; s < SIT; s++) {
            int idx = s*32 + lane;
            int row = idx / CPR2, c = idx % CPR2;
            int plane = c / (2*NTILES);
            int cc = (c % (2*NTILES)) << 2;
            uint32_t d = smem_u32(WtW + row*PW + plane*LOFF + cc);
            CP_ASYNC16(d, Wk + (size_t)row*wstride + (plane ? gap : 0) + n0w + cc);
        }
        CP_COMMIT();
    }
    if (init) {
        #pragma unroll
        for (int i = 0; i < 4*NTILES; i++) C[i] = 0.f;
    }
    int buf = 0;
    for (int t = 0; t < T; t++) {
        CP_WAIT0();
        __syncwarp();
        if (t + 1 < T) {
            const float* gsrc = Wk + (size_t)((t+1)*8)*wstride;
            float* Wd = WtW + (buf^1)*SLICE;
            #pragma unroll
            for (int s = 0; s < SIT; s++) {
                int idx = s*32 + lane;
                int row = idx / CPR2, c = idx % CPR2;
                int plane = c / (2*NTILES);
                int cc = (c % (2*NTILES)) << 2;
                uint32_t d = smem_u32(Wd + row*PW + plane*LOFF + cc);
                CP_ASYNC16(d, gsrc + (size_t)row*wstride + (plane ? gap : 0) + n0w + cc);
            }
            CP_COMMIT();
        }
        const float* W = WtW + buf*SLICE;
        const float* ia = smIn + t*8;
        float ar0 = ia[g*pitch + t4];
        float ar1 = ia[(g+8)*pitch + t4];
        float ar2 = ia[g*pitch + t4 + 4];
        float ar3 = ia[(g+8)*pitch + t4 + 4];
        uint32_t ah0 = f2tf(ar0), ah1 = f2tf(ar1), ah2 = f2tf(ar2), ah3 = f2tf(ar3);
        uint32_t al0 = f2tf(ar0 - __uint_as_float(ah0));
        uint32_t al1 = f2tf(ar1 - __uint_as_float(ah1));
        uint32_t al2 = f2tf(ar2 - __uint_as_float(ah2));
        uint32_t al3 = f2tf(ar3 - __uint_as_float(ah3));
        #pragma unroll
        for (int nt = 0; nt < NTILES; nt++) {
            int n = nt*8 + g;                        // slice-local column
            uint32_t bh0 = __float_as_uint(W[t4*PW + n]);
            uint32_t bh1 = __float_as_uint(W[(t4+4)*PW + n]);
            uint32_t bl0 = __float_as_uint(W[t4*PW + LOFF + n]);
            uint32_t bl1 = __float_as_uint(W[(t4+4)*PW + LOFF + n]);
            float* c = C + nt*4;
            MMA_TF32(c, ah0, ah1, ah2, ah3, bh0, bh1);
            MMA_TF32(c, ah0, ah1, ah2, ah3, bl0, bl1);
            MMA_TF32(c, al0, al1, al2, al3, bh0, bh1);
        }
        buf ^= 1;
    }
    if (fin) {
        __syncthreads();                             // all warps' mainloop reads done (alias safety)
        if (warp < nws) {
            #pragma unroll
            for (int nt = 0; nt < NTILES; nt++) {
                int col = n0w + nt*8 + 2*t4;
                float2 bb = *(const float2*)&bias[col];
                float2 o;
                o.x = C[nt*4+0] + bb.x; o.y = C[nt*4+1] + bb.y;
                if (act) { o.x = gelu_f(o.x); o.y = gelu_f(o.y); }
                *(float2*)&smOut[(size_t)g*opitch + col] = o;
                o.x = C[nt*4+2] + bb.x; o.y = C[nt*4+3] + bb.y;
                if (act) { o.x = gelu_f(o.x); o.y = gelu_f(o.y); }
                *(float2*)&smOut[(size_t)(g+8)*opitch + col] = o;
            }
        }
    }
}

__global__ void __launch_bounds__(NT, 3) fused_kernel(
    const float* __restrict__ x_enc, const float* __restrict__ eps,
    const float* __restrict__ p_aw, const float* __restrict__ p_ab,
    const float* __restrict__ b_sc,
    const float* __restrict__ b_r1, const float* __restrict__ b_r2,
    const float* __restrict__ b_r3,
    const float* __restrict__ flow_w, const float* __restrict__ flow_b,
    float* __restrict__ out)
{
    extern __shared__ float smn[];
    float* sA    = smn + P_A;
    float* sINP  = smn + P_A;
    float* sPB   = smn + P_PB;
    float* sMean = smn + P_MEAN;
    float* sStd  = smn + P_STD;
    float* sScale= smn + P_SCALE;
    float* sB    = smn + P_B;
    float* sWT   = smn + P_WT;

    int tid = threadIdx.x;
    int n0 = blockIdx.x * ROWS;
    float aw = p_aw[0], ab = p_ab[0];
    int warp = tid >> 5, lane = tid & 31;
    float* sWTw = sWT + warp*1152;   // per-warp mma slice base
    float acc[8];

    // ---- 1. load x ----
    for (int t = tid; t < ROWS*L; t += NT) {
        int r = t & 15, l = t >> 4;
        int n = n0 + r;
        int b = n / 7, c = n - b*7;
        sA[r*L + l] = x_enc[(b*L + l)*7 + c];
    }
    __syncthreads();

    // ---- 2. per-row mean/std ----
    #pragma unroll
    for (int rr = 0; rr < 2; rr++) {
        int r = warp*2 + rr;
        const float* row = sA + r*L;
        float s = 0.f, sq = 0.f;
        for (int l2 = lane; l2 < L; l2 += 32) { float v = row[l2]; s += v; sq += v*v; }
        #pragma unroll
        for (int o = 16; o > 0; o >>= 1) {
            s  += __shfl_xor_sync(0xffffffffu, s, o);
            sq += __shfl_xor_sync(0xffffffffu, sq, o);
        }
        if (lane == 0) {
            float mean = s * (1.f/336.f);
            float var = sq * (1.f/336.f) - mean*mean;
            float sd = sqrtf(var + 1e-5f);
            sMean[r] = mean; sStd[r] = sd; sScale[r] = aw / sd;
        }
    }
    __syncthreads();

    // ---- 3. normalize ----
    for (int t = tid; t < ROWS*L; t += NT) {
        int r = t / L;
        sA[t] = (sA[t] - sMean[r]) * sScale[r] + ab;
    }
    __syncthreads();

    // ---- 4. pbar ----
    {
        int r = tid >> 4, j = tid & 15;
        float s = 0.f;
        #pragma unroll
        for (int pp = 0; pp < 41; pp++) s += sA[r*L + pp*8 + j];
        sPB[r*16 + j] = s * (1.f/41.f);
    }

    // ---- 5. shortcut (FFMA exact, KT=24) -> gmem scratch ----
    gemm_s<24>(sA, L, 336, g_Wsct, b_sc, 96, g_short + (size_t)n0*96, 96, 0, sWT, acc, 1, 1);
    // ---- 6. h (FFMA exact, KT=16) -> sINP[:,64:192] ----
    gemm_s<16>(sPB, 16, 16, g_Wct, g_bc, 128, sINP + 64, PITCH_INP, 0, sWT, acc, 1, 1);
    // ---- 7. [mu|lv] (FFMA exact, KT=32) -> sB ----
    gemm_s<32>(sINP + 64, PITCH_INP, 128, g_Wmlt, g_bml, 128, sB, PITCH_B, 0, sWT, acc, 1, 1);
    __syncthreads();

    // ---- 8+9. reparam + flows (FP64, bit-identical) ----
    #pragma unroll
    for (int rr = 0; rr < 2; rr++) {
        int r = warp + rr*8;
        int n = n0 + r;
        float mu0 = sB[r*PITCH_B + lane];
        float mu1 = sB[r*PITCH_B + 32 + lane];
        float lv0 = sB[r*PITCH_B + 64 + lane];
        float lv1 = sB[r*PITCH_B + 96 + lane];
        out[OFF_MU + n*64 + lane]      = mu0;
        out[OFF_MU + n*64 + 32 + lane] = mu1;
        out[OFF_LV + n*64 + lane]      = lv0;
        out[OFF_LV + n*64 + 32 + lane] = lv1;
        double z0 = (double)mu0 + (double)eps[n*64 + lane]      * exp(0.5 * (double)lv0);
        double z1 = (double)mu1 + (double)eps[n*64 + 32 + lane] * exp(0.5 * (double)lv1);
        double ld = 0.0;
        #pragma unroll
        for (int i = 0; i < 8; i++) {
            double w0 = (double)flow_w[i*64 + lane];
            double w1 = (double)flow_w[i*64 + 32 + lane];
            double dot = z0*w0 + z1*w1;
            #pragma unroll
            for (int o = 16; o > 0; o >>= 1) dot += __shfl_xor_sync(0xffffffffu, dot, o);
            double th = tanh(dot + (double)flow_b[i]);
            z0 += th * g_uhat[i*64 + lane];
            z1 += th * g_uhat[i*64 + 32 + lane];
            ld += log(fabs(1.0 + (1.0 - th*th) * g_cflow[i]) + 1e-6);
        }
        sINP[r*PITCH_INP + lane]      = (float)z0;
        sINP[r*PITCH_INP + 32 + lane] = (float)z1;
        if (lane == 0) out[OFF_LD + n] = (float)ld;
    }
    // (gemm_mma's entry barrier orders flow writes before A reads)

    // ---- 10. r1 (3xTF32 mma, warp-private pipeline) -> sB ----
    {
        float C1[16];
        gemm_mma<4>(sINP, PITCH_INP, 192, g_Wr1t2, 512, 256, b_r1, sB, PITCH_B, 1, sWTw, C1, 1, 1, 8);
    }
    // ---- 11+12. r2 chunks (mma) fused with r3 accumulation (mma, C persists) ----
    {
        float C3[8];
        #pragma unroll
        for (int c = 0; c < 2; c++) {
            float C2[16];
            gemm_mma<4>(sB, PITCH_B, 256, g_Wr2t2 + 256*c, 1024, 512, b_r2 + 256*c,
                        sA, PITCH_B, 1, sWTw, C2, 1, 1, 8);
            gemm_mma<2>(sA, PITCH_B, 256, g_Wr3t2 + (size_t)(256*c)*256, 256, 128, b_r3,
                        sA, 100, 0, sWTw, C3, c == 0, c == 1, 6);
        }
    }
    __syncthreads();

    // ---- 13. denorm + scatter (recon in sA pitch 100) ----
    float inv_aw = 1.f / (aw + 1e-10f);
    for (int t = tid; t < ROWS*96; t += NT) {
        int r = t & 15, pcol = t >> 4;
        int n = n0 + r;
        float v = sA[r*100 + pcol] + g_short[(size_t)n*96 + pcol];
        float den = fmaf((v - ab) * inv_aw, sStd[r], sMean[r]);
        int b = n/7, c = n - b*7;
        out[(b*96 + pcol)*7 + c] = den;
    }
}

extern "C" void kernel_launch(void* const* d_in, const int* in_sizes, int n_in,
                              void* d_out, int out_size) {
    const float* x_enc  = (const float*)d_in[0];
    const float* eps    = (const float*)d_in[1];
    const float* aw     = (const float*)d_in[2];
    const float* ab     = (const float*)d_in[3];
    const float* W_sc   = (const float*)d_in[4];
    const float* b_sc   = (const float*)d_in[5];
    const float* W_ts   = (const float*)d_in[6];
    const float* b_ts   = (const float*)d_in[7];
    const float* W_fu   = (const float*)d_in[8];
    const float* b_fu   = (const float*)d_in[9];
    const float* W_mu   = (const float*)d_in[10];
    const float* b_mu   = (const float*)d_in[11];
    const float* W_lv   = (const float*)d_in[12];
    const float* b_lv   = (const float*)d_in[13];
    const float* flow_u = (const float*)d_in[14];
    const float* flow_w = (const float*)d_in[15];
    const float* flow_b = (const float*)d_in[16];
    const float* W_r1   = (const float*)d_in[17];
    const float* b_r1   = (const float*)d_in[18];
    const float* W_r2   = (const float*)d_in[19];
    const float* b_r2   = (const float*)d_in[20];
    const float* W_r3   = (const float*)d_in[21];
    const float* b_r3   = (const float*)d_in[22];
    float* out = (float*)d_out;

    cudaFuncSetAttribute(fused_kernel, cudaFuncAttributeMaxDynamicSharedMemorySize, SMEM_BYTES);

    prep_kernel<<<128, 256>>>(W_sc, W_mu, b_mu, W_lv, b_lv, W_r3,
                              W_fu, b_fu, W_ts, b_ts, flow_u, flow_w, W_r1, W_r2);
    fused_kernel<<<448, NT, SMEM_BYTES>>>(x_enc, eps, aw, ab, b_sc,
                                          b_r1, b_r2, b_r3,
                                          flow_w, flow_b, out);
}

// round 14
// speedup vs baseline: 1.2753x; 1.2058x over previous
#include <cuda_runtime.h>
#include <math.h>
#include <stdint.h>

#define NT 256
#define ROWS 16
#define L 336
#define OFF_MU (1024*96*7)
#define OFF_LV (OFF_MU + 7168*64)
#define OFF_LD (OFF_LV + 7168*64)

// smem pool (floats)
#define P_A     0        // xn[16][336]; aliases: sINP[16][196], r2chunk[16][260], recon[16][100]
#define P_PB    5376
#define P_MEAN  5632
#define P_STD   5648
#define P_SCALE 5664
#define P_B     5680     // ml/r1 out [16][260] = 4160
#define P_WT    9840     // gemm_s tiles only (max 2x32x132 = 8448)
#define SMEM_FLOATS 18288
#define SMEM_BYTES (SMEM_FLOATS*4)

#define PITCH_INP 196    // ≡4 mod 32
#define PITCH_B   260    // ≡4 mod 32

// FFMA-path weights, k-major [k][m]
__device__ __align__(16) float g_Wsct[336*128];   // m padded 96->128
__device__ __align__(16) float g_Wmlt[128*128];   // [mu|lv]
__device__ __align__(16) float g_bml[128];
__device__ __align__(16) float g_Wct[16*128];
__device__ __align__(16) float g_bc[128];
// mma-path weights, lane-packed pre-split tf32 frags:
// [tile][warp][ntile][lane][4] with 4 = (bh@t4, bh@t4+4, bl@t4, bl@t4+4)
__device__ __align__(16) float g_pk1[24*8*512];       // r1: K=192 (24 tiles), M=256
__device__ __align__(16) float g_pk2[2*32*8*512];     // r2: [chunk][32 tiles][...], M=256/chunk
__device__ __align__(16) float g_pk3[2*32*8*256];     // r3: [khalf][32 tiles][...], M=128 (96 pad)
__device__ double g_uhat[8*64];
__device__ double g_cflow[8];
__device__ __align__(16) float g_short[7168*96];

__device__ __forceinline__ uint32_t f2tf(float x) {
    uint32_t r; asm("cvt.rna.tf32.f32 %0, %1;" : "=r"(r) : "f"(x)); return r;
}
__device__ __forceinline__ float tf32f(float x) {
    return __uint_as_float(f2tf(x));
}
__device__ __forceinline__ float split_val(float w, int plane) {
    float hi = tf32f(w);
    return plane ? tf32f(w - hi) : hi;
}

__global__ void prep_kernel(const float* __restrict__ W_sc,
                            const float* __restrict__ W_mu, const float* __restrict__ b_mu,
                            const float* __restrict__ W_lv, const float* __restrict__ b_lv,
                            const float* __restrict__ W_r3,
                            const float* __restrict__ W_fu, const float* __restrict__ b_fu,
                            const float* __restrict__ W_ts, const float* __restrict__ b_ts,
                            const float* __restrict__ flow_u, const float* __restrict__ flow_w,
                            const float* __restrict__ W_r1, const float* __restrict__ W_r2)
{
    int idx = blockIdx.x * blockDim.x + threadIdx.x;
    int stride = gridDim.x * blockDim.x;
    const int S0 = 336*128;
    const int S1 = S0 + 128*128;
    const int S2 = S1 + 128;
    const int S3 = S2 + 16*128;
    const int S4 = S3 + 128;
    const int S5 = S4 + 24*8*512;        // g_pk1
    const int S6 = S5 + 2*32*8*512;      // g_pk2
    const int S7 = S6 + 2*32*8*256;      // g_pk3
    const int S8 = S7 + 8;               // flows
    for (int i = idx; i < S8; i += stride) {
        if (i < S0) {
            int k = i >> 7, m = i & 127;
            g_Wsct[i] = (m < 96) ? W_sc[m*336 + k] : 0.f;
        } else if (i < S1) {
            int j = i - S0;
            int k = j >> 7, m = j & 127;
            g_Wmlt[j] = (m < 64) ? W_mu[m*128 + k] : W_lv[(m-64)*128 + k];
        } else if (i < S2) {
            int j = i - S1;
            g_bml[j] = (j < 64) ? b_mu[j] : b_lv[j-64];
        } else if (i < S3) {
            int j = i - S2;
            int l = j >> 7, h = j & 127;
            float s = 0.f;
            for (int d = 0; d < 128; d++) s += W_fu[h*256 + d] * W_ts[d*16 + l];
            g_Wct[j] = s;
        } else if (i < S4) {
            int h = i - S3;
            float s = 0.f;
            for (int d = 0; d < 128; d++) s += W_fu[h*256 + d] * b_ts[d];
            g_bc[h] = s + b_fu[h];
        } else if (i < S5) {
            int j = i - S4;           // r1 pack: [t(24)][w(8)][c(4)][l(32)][v(4)]
            int v = j & 3, l = (j >> 2) & 31, c = (j >> 7) & 3, w = (j >> 9) & 7, t = j >> 12;
            int g = l >> 2, t4 = l & 3;
            int m = w*32 + c*8 + g;
            int k = t*8 + t4 + (v & 1)*4;
            g_pk1[j] = split_val(W_r1[m*192 + k], v >> 1);
        } else if (i < S6) {
            int j = i - S5;           // r2 pack: [ch(2)][t(32)][w(8)][c(4)][l(32)][v(4)]
            int v = j & 3, l = (j >> 2) & 31, c = (j >> 7) & 3, w = (j >> 9) & 7, t = (j >> 12) & 31, ch = j >> 17;
            int g = l >> 2, t4 = l & 3;
            int m = ch*256 + w*32 + c*8 + g;
            int k = t*8 + t4 + (v & 1)*4;
            g_pk2[j] = split_val(W_r2[m*256 + k], v >> 1);
        } else if (i < S7) {
            int j = i - S6;           // r3 pack: [kh(2)][t(32)][w(8)][c(2)][l(32)][v(4)]
            int v = j & 3, l = (j >> 2) & 31, c = (j >> 7) & 1, w = (j >> 8) & 7, t = (j >> 11) & 31, kh = j >> 16;
            int g = l >> 2, t4 = l & 3;
            int m = w*16 + c*8 + g;
            int k = kh*256 + t*8 + t4 + (v & 1)*4;
            float wv = (m < 96) ? W_r3[m*512 + k] : 0.f;
            g_pk3[j] = split_val(wv, v >> 1);
        } else {
            int fi = i - S7;
            double s = 0.0, wsq = 0.0;
            for (int d = 0; d < 64; d++) {
                double u = (double)flow_u[fi*64+d], w = (double)flow_w[fi*64+d];
                s += u*w; wsq += w*w;
            }
            double sp = (s > 0.0) ? s + log1p(exp(-s)) : log1p(exp(s));
            double m = -1.0 + sp;
            double coef = m / (wsq + 1e-6);
            for (int d = 0; d < 64; d++)
                g_uhat[fi*64+d] = (double)flow_u[fi*64+d] + coef*(double)flow_w[fi*64+d];
            g_cflow[fi] = s + coef * wsq;
        }
    }
}

__device__ __forceinline__ float gelu_f(float x) {
    return 0.5f * x * (1.f + erff(x * 0.70710678118654752f));
}
__device__ __forceinline__ uint32_t smem_u32(const void* p) {
    return (uint32_t)__cvta_generic_to_shared(p);
}
#define CP_ASYNC16(d, s) asm volatile("cp.async.ca.shared.global [%0], [%1], 16;\n" :: "r"(d), "l"(s))
#define CP_COMMIT()      asm volatile("cp.async.commit_group;\n" ::: "memory")
#define CP_WAIT0()       asm volatile("cp.async.wait_group 0;\n" ::: "memory")

#define MMA_TF32(c, a0,a1,a2,a3, b0,b1) \
    asm volatile("mma.sync.aligned.m16n8k8.row.col.f32.tf32.tf32.f32 " \
        "{%0,%1,%2,%3}, {%4,%5,%6,%7}, {%8,%9}, {%0,%1,%2,%3};" \
        : "+f"((c)[0]), "+f"((c)[1]), "+f"((c)[2]), "+f"((c)[3]) \
        : "r"(a0), "r"(a1), "r"(a2), "r"(a3), "r"(b0), "r"(b1))

// ---------------- FFMA fp32 GEMM (bit-exact path), templated k-tile depth ----------------
template<int KT>
__device__ __forceinline__ void gemm_s(
    const float* smIn, int pitch, int K,
    const float* __restrict__ Wk, const float* __restrict__ bias,
    int Mreal, float* smOut, int opitch, int act, float* Wt,
    float* acc, int init, int fin)
{
    constexpr int BUFS = KT*132;
    constexpr int SIT  = KT/8;
    const int tid = threadIdx.x;
    const int rg = tid >> 6;
    const int mloc = (tid & 63) << 1;
    const float* in0 = smIn + rg*4*pitch;
    const int T = K / KT;
    {
        #pragma unroll
        for (int s = 0; s < SIT; s++) {
            int idx = s*256 + tid;
            int row = idx >> 5, col = (idx & 31) << 2;
            CP_ASYNC16(smem_u32(Wt + row*132 + col), Wk + (size_t)row*128 + col);
        }
        CP_COMMIT();
    }
    if (init) {
        #pragma unroll
        for (int i = 0; i < 8; i++) acc[i] = 0.f;
    }
    int buf = 0;
    for (int t = 0; t < T; t++) {
        CP_WAIT0();
        __syncthreads();
        if (t + 1 < T) {
            const float* g = Wk + (size_t)((t+1)*KT)*128;
            float* Wd = Wt + (buf^1)*BUFS;
            #pragma unroll
            for (int s = 0; s < SIT; s++) {
                int idx = s*256 + tid;
                int row = idx >> 5, col = (idx & 31) << 2;
                CP_ASYNC16(smem_u32(Wd + row*132 + col), g + (size_t)row*128 + col);
            }
            CP_COMMIT();
        }
        const float* W = Wt + buf*BUFS;
        const float* i0 = in0 + t*KT;
        #pragma unroll
        for (int kk = 0; kk < KT; kk += 2) {
            float2 w0 = *(const float2*)&W[kk*132 + mloc];
            float2 w1 = *(const float2*)&W[(kk+1)*132 + mloc];
            float2 x0 = *(const float2*)(i0 + kk);
            float2 x1 = *(const float2*)(i0 + pitch + kk);
            float2 x2 = *(const float2*)(i0 + 2*pitch + kk);
            float2 x3 = *(const float2*)(i0 + 3*pitch + kk);
            acc[0] = fmaf(x0.x, w0.x, acc[0]); acc[0] = fmaf(x0.y, w1.x, acc[0]);
            acc[1] = fmaf(x0.x, w0.y, acc[1]); acc[1] = fmaf(x0.y, w1.y, acc[1]);
            acc[2] = fmaf(x1.x, w0.x, acc[2]); acc[2] = fmaf(x1.y, w1.x, acc[2]);
            acc[3] = fmaf(x1.x, w0.y, acc[3]); acc[3] = fmaf(x1.y, w1.y, acc[3]);
            acc[4] = fmaf(x2.x, w0.x, acc[4]); acc[4] = fmaf(x2.y, w1.x, acc[4]);
            acc[5] = fmaf(x2.x, w0.y, acc[5]); acc[5] = fmaf(x2.y, w1.y, acc[5]);
            acc[6] = fmaf(x3.x, w0.x, acc[6]); acc[6] = fmaf(x3.y, w1.x, acc[6]);
            acc[7] = fmaf(x3.x, w0.y, acc[7]); acc[7] = fmaf(x3.y, w1.y, acc[7]);
        }
        buf ^= 1;
    }
    __syncthreads();
    if (fin && mloc < Mreal) {
        float b0 = bias[mloc], b1 = bias[mloc+1];
        int r0 = rg*4;
        #pragma unroll
        for (int r = 0; r < 4; r++) {
            float2 o;
            o.x = acc[2*r]   + b0;
            o.y = acc[2*r+1] + b1;
            if (act) { o.x = gelu_f(o.x); o.y = gelu_f(o.y); }
            *(float2*)&smOut[(size_t)(r0+r)*opitch + mloc] = o;
        }
    }
}

// ---------------- 3xTF32 mma GEMM, register-direct lane-packed weights ----------------
// Weights come from gmem pk array (lane-packed frags) via LDG.128 straight into
// registers; NO smem staging, NO mainloop barriers. Double-buffered (qa/qb),
// 2-deep manual unroll (T always even). Entry __syncthreads protects smIn,
// fin pre-store __syncthreads protects aliased smOut.
template<int NTILES>
__device__ __forceinline__ void gemm_mma_reg(
    const float* smIn, int pitch, int K,
    const float* __restrict__ pk,
    const float* __restrict__ bias,
    float* smOut, int opitch, int act,
    float* C, int init, int fin, int nws)
{
    constexpr int TBV = NTILES*32;                  // tile block in float4s (128 / 64)
    const int tid = threadIdx.x;
    const int lane = tid & 31;
    const int warp = tid >> 5;
    const int g = lane >> 2, t4 = lane & 3;
    const int n0w = warp * (8*NTILES);
    const int T = K >> 3;                            // even for all call sites
    const float4* pw = (const float4*)pk + (size_t)warp*TBV + lane;
    const int wstep = 8*TBV;                         // tile stride in float4s

    __syncthreads();                                 // smIn ready
    float4 qa[NTILES], qb[NTILES];
    #pragma unroll
    for (int c = 0; c < NTILES; c++) qa[c] = __ldg(pw + c*32);
    if (init) {
        #pragma unroll
        for (int i = 0; i < 4*NTILES; i++) C[i] = 0.f;
    }

#define MMA_STEP(tt, q) do { \
        const float* ia = smIn + (tt)*8; \
        float ar0 = ia[g*pitch + t4]; \
        float ar1 = ia[(g+8)*pitch + t4]; \
        float ar2 = ia[g*pitch + t4 + 4]; \
        float ar3 = ia[(g+8)*pitch + t4 + 4]; \
        uint32_t ah0 = f2tf(ar0), ah1 = f2tf(ar1), ah2 = f2tf(ar2), ah3 = f2tf(ar3); \
        uint32_t al0 = f2tf(ar0 - __uint_as_float(ah0)); \
        uint32_t al1 = f2tf(ar1 - __uint_as_float(ah1)); \
        uint32_t al2 = f2tf(ar2 - __uint_as_float(ah2)); \
        uint32_t al3 = f2tf(ar3 - __uint_as_float(ah3)); \
        _Pragma("unroll") \
        for (int nt = 0; nt < NTILES; nt++) { \
            uint32_t bh0 = __float_as_uint((q)[nt].x); \
            uint32_t bh1 = __float_as_uint((q)[nt].y); \
            uint32_t bl0 = __float_as_uint((q)[nt].z); \
            uint32_t bl1 = __float_as_uint((q)[nt].w); \
            float* c = C + nt*4; \
            MMA_TF32(c, ah0, ah1, ah2, ah3, bh0, bh1); \
            MMA_TF32(c, ah0, ah1, ah2, ah3, bl0, bl1); \
            MMA_TF32(c, al0, al1, al2, al3, bh0, bh1); \
        } \
    } while (0)

    for (int t = 0; t < T; t += 2) {
        const float4* pn = pw + (size_t)(t+1)*wstep;
        #pragma unroll
        for (int c = 0; c < NTILES; c++) qb[c] = __ldg(pn + c*32);
        MMA_STEP(t, qa);
        if (t + 2 < T) {
            const float4* pn2 = pw + (size_t)(t+2)*wstep;
            #pragma unroll
            for (int c = 0; c < NTILES; c++) qa[c] = __ldg(pn2 + c*32);
        }
        MMA_STEP(t+1, qb);
    }
#undef MMA_STEP

    if (fin) {
        __syncthreads();                             // all warps' smIn reads done (alias safety)
        if (warp < nws) {
            #pragma unroll
            for (int nt = 0; nt < NTILES; nt++) {
                int col = n0w + nt*8 + 2*t4;
                float2 bb = *(const float2*)&bias[col];
                float2 o;
                o.x = C[nt*4+0] + bb.x; o.y = C[nt*4+1] + bb.y;
                if (act) { o.x = gelu_f(o.x); o.y = gelu_f(o.y); }
                *(float2*)&smOut[(size_t)g*opitch + col] = o;
                o.x = C[nt*4+2] + bb.x; o.y = C[nt*4+3] + bb.y;
                if (act) { o.x = gelu_f(o.x); o.y = gelu_f(o.y); }
                *(float2*)&smOut[(size_t)(g+8)*opitch + col] = o;
            }
        }
    }
}

__global__ void __launch_bounds__(NT, 3) fused_kernel(
    const float* __restrict__ x_enc, const float* __restrict__ eps,
    const float* __restrict__ p_aw, const float* __restrict__ p_ab,
    const float* __restrict__ b_sc,
    const float* __restrict__ b_r1, const float* __restrict__ b_r2,
    const float* __restrict__ b_r3,
    const float* __restrict__ flow_w, const float* __restrict__ flow_b,
    float* __restrict__ out)
{
    extern __shared__ float smn[];
    float* sA    = smn + P_A;
    float* sINP  = smn + P_A;
    float* sPB   = smn + P_PB;
    float* sMean = smn + P_MEAN;
    float* sStd  = smn + P_STD;
    float* sScale= smn + P_SCALE;
    float* sB    = smn + P_B;
    float* sWT   = smn + P_WT;

    int tid = threadIdx.x;
    int n0 = blockIdx.x * ROWS;
    float aw = p_aw[0], ab = p_ab[0];
    int warp = tid >> 5, lane = tid & 31;
    float acc[8];

    // ---- 1. load x ----
    for (int t = tid; t < ROWS*L; t += NT) {
        int r = t & 15, l = t >> 4;
        int n = n0 + r;
        int b = n / 7, c = n - b*7;
        sA[r*L + l] = x_enc[(b*L + l)*7 + c];
    }
    __syncthreads();

    // ---- 2. per-row mean/std ----
    #pragma unroll
    for (int rr = 0; rr < 2; rr++) {
        int r = warp*2 + rr;
        const float* row = sA + r*L;
        float s = 0.f, sq = 0.f;
        for (int l2 = lane; l2 < L; l2 += 32) { float v = row[l2]; s += v; sq += v*v; }
        #pragma unroll
        for (int o = 16; o > 0; o >>= 1) {
            s  += __shfl_xor_sync(0xffffffffu, s, o);
            sq += __shfl_xor_sync(0xffffffffu, sq, o);
        }
        if (lane == 0) {
            float mean = s * (1.f/336.f);
            float var = sq * (1.f/336.f) - mean*mean;
            float sd = sqrtf(var + 1e-5f);
            sMean[r] = mean; sStd[r] = sd; sScale[r] = aw / sd;
        }
    }
    __syncthreads();

    // ---- 3. normalize ----
    for (int t = tid; t < ROWS*L; t += NT) {
        int r = t / L;
        sA[t] = (sA[t] - sMean[r]) * sScale[r] + ab;
    }
    __syncthreads();

    // ---- 4. pbar ----
    {
        int r = tid >> 4, j = tid & 15;
        float s = 0.f;
        #pragma unroll
        for (int pp = 0; pp < 41; pp++) s += sA[r*L + pp*8 + j];
        sPB[r*16 + j] = s * (1.f/41.f);
    }

    // ---- 5. shortcut (FFMA exact, KT=24) -> gmem scratch ----
    gemm_s<24>(sA, L, 336, g_Wsct, b_sc, 96, g_short + (size_t)n0*96, 96, 0, sWT, acc, 1, 1);
    // ---- 6. h (FFMA exact, KT=16) -> sINP[:,64:192] ----
    gemm_s<16>(sPB, 16, 16, g_Wct, g_bc, 128, sINP + 64, PITCH_INP, 0, sWT, acc, 1, 1);
    // ---- 7. [mu|lv] (FFMA exact, KT=32) -> sB ----
    gemm_s<32>(sINP + 64, PITCH_INP, 128, g_Wmlt, g_bml, 128, sB, PITCH_B, 0, sWT, acc, 1, 1);
    __syncthreads();

    // ---- 8+9. reparam + flows (FP64, bit-identical) ----
    #pragma unroll
    for (int rr = 0; rr < 2; rr++) {
        int r = warp + rr*8;
        int n = n0 + r;
        float mu0 = sB[r*PITCH_B + lane];
        float mu1 = sB[r*PITCH_B + 32 + lane];
        float lv0 = sB[r*PITCH_B + 64 + lane];
        float lv1 = sB[r*PITCH_B + 96 + lane];
        out[OFF_MU + n*64 + lane]      = mu0;
        out[OFF_MU + n*64 + 32 + lane] = mu1;
        out[OFF_LV + n*64 + lane]      = lv0;
        out[OFF_LV + n*64 + 32 + lane] = lv1;
        double z0 = (double)mu0 + (double)eps[n*64 + lane]      * exp(0.5 * (double)lv0);
        double z1 = (double)mu1 + (double)eps[n*64 + 32 + lane] * exp(0.5 * (double)lv1);
        double ld = 0.0;
        #pragma unroll
        for (int i = 0; i < 8; i++) {
            double w0 = (double)flow_w[i*64 + lane];
            double w1 = (double)flow_w[i*64 + 32 + lane];
            double dot = z0*w0 + z1*w1;
            #pragma unroll
            for (int o = 16; o > 0; o >>= 1) dot += __shfl_xor_sync(0xffffffffu, dot, o);
            double th = tanh(dot + (double)flow_b[i]);
            z0 += th * g_uhat[i*64 + lane];
            z1 += th * g_uhat[i*64 + 32 + lane];
            ld += log(fabs(1.0 + (1.0 - th*th) * g_cflow[i]) + 1e-6);
        }
        sINP[r*PITCH_INP + lane]      = (float)z0;
        sINP[r*PITCH_INP + 32 + lane] = (float)z1;
        if (lane == 0) out[OFF_LD + n] = (float)ld;
    }
    // (gemm_mma_reg entry barrier orders flow writes before A reads)

    // ---- 10. r1 (3xTF32 mma, register-direct weights) -> sB ----
    {
        float C1[16];
        gemm_mma_reg<4>(sINP, PITCH_INP, 192, g_pk1, b_r1, sB, PITCH_B, 1, C1, 1, 1, 8);
    }
    // ---- 11+12. r2 chunks (mma) fused with r3 accumulation (mma, C persists) ----
    {
        float C3[8];
        #pragma unroll
        for (int c = 0; c < 2; c++) {
            float C2[16];
            gemm_mma_reg<4>(sB, PITCH_B, 256, g_pk2 + (size_t)c*32*8*512, b_r2 + 256*c,
                            sA, PITCH_B, 1, C2, 1, 1, 8);
            gemm_mma_reg<2>(sA, PITCH_B, 256, g_pk3 + (size_t)c*32*8*256, b_r3,
                            sA, 100, 0, C3, c == 0, c == 1, 6);
        }
    }
    __syncthreads();

    // ---- 13. denorm + scatter (recon in sA pitch 100) ----
    float inv_aw = 1.f / (aw + 1e-10f);
    for (int t = tid; t < ROWS*96; t += NT) {
        int r = t & 15, pcol = t >> 4;
        int n = n0 + r;
        float v = sA[r*100 + pcol] + g_short[(size_t)n*96 + pcol];
        float den = fmaf((v - ab) * inv_aw, sStd[r], sMean[r]);
        int b = n/7, c = n - b*7;
        out[(b*96 + pcol)*7 + c] = den;
    }
}

extern "C" void kernel_launch(void* const* d_in, const int* in_sizes, int n_in,
                              void* d_out, int out_size) {
    const float* x_enc  = (const float*)d_in[0];
    const float* eps    = (const float*)d_in[1];
    const float* aw     = (const float*)d_in[2];
    const float* ab     = (const float*)d_in[3];
    const float* W_sc   = (const float*)d_in[4];
    const float* b_sc   = (const float*)d_in[5];
    const float* W_ts   = (const float*)d_in[6];
    const float* b_ts   = (const float*)d_in[7];
    const float* W_fu   = (const float*)d_in[8];
    const float* b_fu   = (const float*)d_in[9];
    const float* W_mu   = (const float*)d_in[10];
    const float* b_mu   = (const float*)d_in[11];
    const float* W_lv   = (const float*)d_in[12];
    const float* b_lv   = (const float*)d_in[13];
    const float* flow_u = (const float*)d_in[14];
    const float* flow_w = (const float*)d_in[15];
    const float* flow_b = (const float*)d_in[16];
    const float* W_r1   = (const float*)d_in[17];
    const float* b_r1   = (const float*)d_in[18];
    const float* W_r2   = (const float*)d_in[19];
    const float* b_r2   = (const float*)d_in[20];
    const float* W_r3   = (const float*)d_in[21];
    const float* b_r3   = (const float*)d_in[22];
    float* out = (float*)d_out;

    cudaFuncSetAttribute(fused_kernel, cudaFuncAttributeMaxDynamicSharedMemorySize, SMEM_BYTES);

    prep_kernel<<<128, 256>>>(W_sc, W_mu, b_mu, W_lv, b_lv, W_r3,
                              W_fu, b_fu, W_ts, b_ts, flow_u, flow_w, W_r1, W_r2);
    fused_kernel<<<448, NT, SMEM_BYTES>>>(x_enc, eps, aw, ab, b_sc,
                                          b_r1, b_r2, b_r3,
                                          flow_w, flow_b, out);
}

// round 15
// speedup vs baseline: 1.3752x; 1.0783x over previous
#include <cuda_runtime.h>
#include <math.h>
#include <stdint.h>

#define NT 256
#define ROWS 16
#define L 336
#define XP 340           // xn pitch (bank-clean for mma A loads: 340 % 32 = 20)
#define OFF_MU (1024*96*7)
#define OFF_LV (OFF_MU + 7168*64)
#define OFF_LD (OFF_LV + 7168*64)

// smem pool (floats)
// A region [0..6272): xn[16][340]=5440; gemm_s WT alias (4224, only during h/mu-lv);
//                     inp2 [32][196]=6272 (hi rows 0-15, lo rows 16-31);
//                     r2chunk2 [32][132]=4224; recon [16][100]=1600.
#define P_A     0
#define P_PB    6272
#define P_MEAN  6528
#define P_STD   6544
#define P_SCALE 6560
#define P_B     6576     // [mu|lv] rows 0-15 pitch 260; hbuf (h fp32) rows 16-31; later r1out2 [32][260]
#define SMEM_FLOATS 14896
#define SMEM_BYTES (SMEM_FLOATS*4)

#define PITCH_INP 196
#define PITCH_B   260

// FFMA-path weights, k-major [k][m]
__device__ __align__(16) float g_Wmlt[128*128];   // [mu|lv]
__device__ __align__(16) float g_bml[128];
__device__ __align__(16) float g_Wct[16*128];
__device__ __align__(16) float g_bc[128];
// mma-path lane-packed pre-split tf32 frags: [tile][warp][ntile][lane][4]
__device__ __align__(16) float g_pk0[42*8*256];     // shortcut: K=336, M=128(96 pad), NTILES=2
__device__ __align__(16) float g_pk1[24*8*512];     // r1: K=192, M=256, NTILES=4
__device__ __align__(16) float g_pk2[4*32*8*256];   // r2: [ch(4)] K=256, M=128/ch, NTILES=2
__device__ __align__(16) float g_pk3[4*16*8*256];   // r3: [kq(4)] K=128/q, M=128(96 pad), NTILES=2
__device__ double g_uhat[8*64];
__device__ double g_cflow[8];
__device__ __align__(16) float g_short[7168*96];

__device__ __forceinline__ uint32_t f2tf(float x) {
    uint32_t r; asm("cvt.rna.tf32.f32 %0, %1;" : "=r"(r) : "f"(x)); return r;
}
__device__ __forceinline__ float tf32f(float x) {
    return __uint_as_float(f2tf(x));
}
__device__ __forceinline__ float split_val(float w, int plane) {
    float hi = tf32f(w);
    return plane ? tf32f(w - hi) : hi;
}

__global__ void prep_kernel(const float* __restrict__ W_sc,
                            const float* __restrict__ W_mu, const float* __restrict__ b_mu,
                            const float* __restrict__ W_lv, const float* __restrict__ b_lv,
                            const float* __restrict__ W_r3,
                            const float* __restrict__ W_fu, const float* __restrict__ b_fu,
                            const float* __restrict__ W_ts, const float* __restrict__ b_ts,
                            const float* __restrict__ flow_u, const float* __restrict__ flow_w,
                            const float* __restrict__ W_r1, const float* __restrict__ W_r2)
{
    int idx = blockIdx.x * blockDim.x + threadIdx.x;
    int stride = gridDim.x * blockDim.x;
    const int S0 = 128*128;              // Wmlt
    const int S1 = S0 + 128;             // bml
    const int S2 = S1 + 16*128;          // Wct
    const int S3 = S2 + 128;             // bc
    const int S4 = S3 + 42*8*256;        // pk0
    const int S5 = S4 + 24*8*512;        // pk1
    const int S6 = S5 + 4*32*8*256;      // pk2
    const int S7 = S6 + 4*16*8*256;      // pk3
    const int S8 = S7 + 8;               // flows
    for (int i = idx; i < S8; i += stride) {
        if (i < S0) {
            int k = i >> 7, m = i & 127;
            g_Wmlt[i] = (m < 64) ? W_mu[m*128 + k] : W_lv[(m-64)*128 + k];
        } else if (i < S1) {
            int j = i - S0;
            g_bml[j] = (j < 64) ? b_mu[j] : b_lv[j-64];
        } else if (i < S2) {
            int j = i - S1;
            int l = j >> 7, h = j & 127;
            float s = 0.f;
            for (int d = 0; d < 128; d++) s += W_fu[h*256 + d] * W_ts[d*16 + l];
            g_Wct[j] = s;
        } else if (i < S3) {
            int h = i - S2;
            float s = 0.f;
            for (int d = 0; d < 128; d++) s += W_fu[h*256 + d] * b_ts[d];
            g_bc[h] = s + b_fu[h];
        } else if (i < S4) {
            int j = i - S3;           // pk0: [t(42)][w(8)][c(1b)][l(32)][v(4)]
            int v = j & 3, l = (j >> 2) & 31, c = (j >> 7) & 1, w = (j >> 8) & 7, t = j >> 11;
            int g = l >> 2, t4 = l & 3;
            int m = w*16 + c*8 + g;
            int k = t*8 + t4 + (v & 1)*4;
            float wv = (m < 96) ? W_sc[m*336 + k] : 0.f;
            g_pk0[j] = split_val(wv, v >> 1);
        } else if (i < S5) {
            int j = i - S4;           // pk1: [t(24)][w(8)][c(2b)][l(32)][v(4)]
            int v = j & 3, l = (j >> 2) & 31, c = (j >> 7) & 3, w = (j >> 9) & 7, t = j >> 12;
            int g = l >> 2, t4 = l & 3;
            int m = w*32 + c*8 + g;
            int k = t*8 + t4 + (v & 1)*4;
            g_pk1[j] = split_val(W_r1[m*192 + k], v >> 1);
        } else if (i < S6) {
            int j = i - S5;           // pk2: [ch(2b)][t(32)][w(8)][c(1b)][l(32)][v(4)]
            int v = j & 3, l = (j >> 2) & 31, c = (j >> 7) & 1, w = (j >> 8) & 7, t = (j >> 11) & 31, ch = j >> 16;
            int g = l >> 2, t4 = l & 3;
            int m = ch*128 + w*16 + c*8 + g;
            int k = t*8 + t4 + (v & 1)*4;
            g_pk2[j] = split_val(W_r2[m*256 + k], v >> 1);
        } else if (i < S7) {
            int j = i - S6;           // pk3: [kq(2b)][t(16)][w(8)][c(1b)][l(32)][v(4)]
            int v = j & 3, l = (j >> 2) & 31, c = (j >> 7) & 1, w = (j >> 8) & 7, t = (j >> 11) & 15, kq = j >> 15;
            int g = l >> 2, t4 = l & 3;
            int m = w*16 + c*8 + g;
            int k = kq*128 + t*8 + t4 + (v & 1)*4;
            float wv = (m < 96) ? W_r3[m*512 + k] : 0.f;
            g_pk3[j] = split_val(wv, v >> 1);
        } else {
            int fi = i - S7;
            double s = 0.0, wsq = 0.0;
            for (int d = 0; d < 64; d++) {
                double u = (double)flow_u[fi*64+d], w = (double)flow_w[fi*64+d];
                s += u*w; wsq += w*w;
            }
            double sp = (s > 0.0) ? s + log1p(exp(-s)) : log1p(exp(s));
            double m = -1.0 + sp;
            double coef = m / (wsq + 1e-6);
            for (int d = 0; d < 64; d++)
                g_uhat[fi*64+d] = (double)flow_u[fi*64+d] + coef*(double)flow_w[fi*64+d];
            g_cflow[fi] = s + coef * wsq;
        }
    }
}

__device__ __forceinline__ float gelu_f(float x) {
    return 0.5f * x * (1.f + erff(x * 0.70710678118654752f));
}
__device__ __forceinline__ uint32_t smem_u32(const void* p) {
    return (uint32_t)__cvta_generic_to_shared(p);
}
#define CP_ASYNC16(d, s) asm volatile("cp.async.ca.shared.global [%0], [%1], 16;\n" :: "r"(d), "l"(s))
#define CP_COMMIT()      asm volatile("cp.async.commit_group;\n" ::: "memory")
#define CP_WAIT0()       asm volatile("cp.async.wait_group 0;\n" ::: "memory")

#define MMA_TF32(c, a0,a1,a2,a3, b0,b1) \
    asm volatile("mma.sync.aligned.m16n8k8.row.col.f32.tf32.tf32.f32 " \
        "{%0,%1,%2,%3}, {%4,%5,%6,%7}, {%8,%9}, {%0,%1,%2,%3};" \
        : "+f"((c)[0]), "+f"((c)[1]), "+f"((c)[2]), "+f"((c)[3]) \
        : "r"(a0), "r"(a1), "r"(a2), "r"(a3), "r"(b0), "r"(b1))

// ---------------- FFMA fp32 GEMM (bit-exact; h and mu/lv only), KT=16 ----------------
__device__ __forceinline__ void gemm_s(
    const float* smIn, int pitch, int K,
    const float* __restrict__ Wk, const float* __restrict__ bias,
    float* smOut, int opitch, float* Wt, float* acc)
{
    const int tid = threadIdx.x;
    const int rg = tid >> 6;
    const int mloc = (tid & 63) << 1;
    const int srow = tid >> 5;
    const int scol = (tid & 31) << 2;
    const float* in0 = smIn + rg*4*pitch;
    const int T = K >> 4;
    {
        #pragma unroll
        for (int s2 = 0; s2 < 2; s2++) {
            CP_ASYNC16(smem_u32(Wt + (srow + 8*s2)*132 + scol), Wk + (size_t)(srow + 8*s2)*128 + scol);
        }
        CP_COMMIT();
    }
    #pragma unroll
    for (int i = 0; i < 8; i++) acc[i] = 0.f;
    int buf = 0;
    for (int t = 0; t < T; t++) {
        CP_WAIT0();
        __syncthreads();
        if (t + 1 < T) {
            const float* g = Wk + (size_t)((t+1)*16)*128;
            float* Wd = Wt + (buf^1)*2112;
            #pragma unroll
            for (int s2 = 0; s2 < 2; s2++) {
                CP_ASYNC16(smem_u32(Wd + (srow + 8*s2)*132 + scol), g + (size_t)(srow + 8*s2)*128 + scol);
            }
            CP_COMMIT();
        }
        const float* W = Wt + buf*2112;
        const float* i0 = in0 + t*16;
        #pragma unroll
        for (int kk = 0; kk < 16; kk += 2) {
            float2 w0 = *(const float2*)&W[kk*132 + mloc];
            float2 w1 = *(const float2*)&W[(kk+1)*132 + mloc];
            float2 x0 = *(const float2*)(i0 + kk);
            float2 x1 = *(const float2*)(i0 + pitch + kk);
            float2 x2 = *(const float2*)(i0 + 2*pitch + kk);
            float2 x3 = *(const float2*)(i0 + 3*pitch + kk);
            acc[0] = fmaf(x0.x, w0.x, acc[0]); acc[0] = fmaf(x0.y, w1.x, acc[0]);
            acc[1] = fmaf(x0.x, w0.y, acc[1]); acc[1] = fmaf(x0.y, w1.y, acc[1]);
            acc[2] = fmaf(x1.x, w0.x, acc[2]); acc[2] = fmaf(x1.y, w1.x, acc[2]);
            acc[3] = fmaf(x1.x, w0.y, acc[3]); acc[3] = fmaf(x1.y, w1.y, acc[3]);
            acc[4] = fmaf(x2.x, w0.x, acc[4]); acc[4] = fmaf(x2.y, w1.x, acc[4]);
            acc[5] = fmaf(x2.x, w0.y, acc[5]); acc[5] = fmaf(x2.y, w1.y, acc[5]);
            acc[6] = fmaf(x3.x, w0.x, acc[6]); acc[6] = fmaf(x3.y, w1.x, acc[6]);
            acc[7] = fmaf(x3.x, w0.y, acc[7]); acc[7] = fmaf(x3.y, w1.y, acc[7]);
        }
        buf ^= 1;
    }
    __syncthreads();
    {
        float b0 = bias[mloc], b1 = bias[mloc+1];
        int r0 = rg*4;
        #pragma unroll
        for (int r = 0; r < 4; r++) {
            float2 o;
            o.x = acc[2*r]   + b0;
            o.y = acc[2*r+1] + b1;
            *(float2*)&smOut[(size_t)(r0+r)*opitch + mloc] = o;
        }
    }
}

// ---------------- 3xTF32 mma GEMM, register-direct weights ----------------
// SPLITA: A planes pre-split in smem (hi rows 0-15, lo rows 16-31); else runtime split.
// SPLITOUT: store tf32 hi/lo planes (rows r and r+16); else plain fp32 store.
// No mainloop barriers; entry __syncthreads protects smIn, fin pre-store __syncthreads.
template<int NTILES, int SPLITA, int SPLITOUT>
__device__ __forceinline__ void gemm_mma_reg(
    const float* smIn, int pitch, int K,
    const float* __restrict__ pk,
    const float* __restrict__ bias,
    float* smOut, int opitch, int act,
    float* C, int init, int fin, int nws)
{
    constexpr int TBV = NTILES*32;
    const int tid = threadIdx.x;
    const int lane = tid & 31;
    const int warp = tid >> 5;
    const int g = lane >> 2, t4 = lane & 3;
    const int n0w = warp * (8*NTILES);
    const int T = K >> 3;
    const float4* pw = (const float4*)pk + (size_t)warp*TBV + lane;
    const int wstep = 8*TBV;

    __syncthreads();
    float4 qa[NTILES], qb[NTILES];
    #pragma unroll
    for (int c = 0; c < NTILES; c++) qa[c] = __ldg(pw + c*32);
    if (init) {
        #pragma unroll
        for (int i = 0; i < 4*NTILES; i++) C[i] = 0.f;
    }

    auto mma_step = [&](int tt, float4* q) {
        const float* ia = smIn + tt*8;
        uint32_t ah0, ah1, ah2, ah3, al0, al1, al2, al3;
        if constexpr (SPLITA) {
            ah0 = __float_as_uint(ia[g*pitch + t4]);
            ah1 = __float_as_uint(ia[(g+8)*pitch + t4]);
            ah2 = __float_as_uint(ia[g*pitch + t4 + 4]);
            ah3 = __float_as_uint(ia[(g+8)*pitch + t4 + 4]);
            al0 = __float_as_uint(ia[(g+16)*pitch + t4]);
            al1 = __float_as_uint(ia[(g+24)*pitch + t4]);
            al2 = __float_as_uint(ia[(g+16)*pitch + t4 + 4]);
            al3 = __float_as_uint(ia[(g+24)*pitch + t4 + 4]);
        } else {
            float ar0 = ia[g*pitch + t4];
            float ar1 = ia[(g+8)*pitch + t4];
            float ar2 = ia[g*pitch + t4 + 4];
            float ar3 = ia[(g+8)*pitch + t4 + 4];
            ah0 = f2tf(ar0); ah1 = f2tf(ar1); ah2 = f2tf(ar2); ah3 = f2tf(ar3);
            al0 = f2tf(ar0 - __uint_as_float(ah0));
            al1 = f2tf(ar1 - __uint_as_float(ah1));
            al2 = f2tf(ar2 - __uint_as_float(ah2));
            al3 = f2tf(ar3 - __uint_as_float(ah3));
        }
        #pragma unroll
        for (int nt = 0; nt < NTILES; nt++) {
            uint32_t bh0 = __float_as_uint(q[nt].x);
            uint32_t bh1 = __float_as_uint(q[nt].y);
            uint32_t bl0 = __float_as_uint(q[nt].z);
            uint32_t bl1 = __float_as_uint(q[nt].w);
            float* c = C + nt*4;
            MMA_TF32(c, ah0, ah1, ah2, ah3, bh0, bh1);
            MMA_TF32(c, ah0, ah1, ah2, ah3, bl0, bl1);
            MMA_TF32(c, al0, al1, al2, al3, bh0, bh1);
        }
    };

    for (int t = 0; t < T; t += 2) {
        const float4* pn = pw + (size_t)(t+1)*wstep;
        #pragma unroll
        for (int c = 0; c < NTILES; c++) qb[c] = __ldg(pn + c*32);
        mma_step(t, qa);
        if (t + 2 < T) {
            const float4* pn2 = pw + (size_t)(t+2)*wstep;
            #pragma unroll
            for (int c = 0; c < NTILES; c++) qa[c] = __ldg(pn2 + c*32);
        }
        mma_step(t+1, qb);
    }

    if (fin) {
        __syncthreads();
        if (warp < nws) {
            #pragma unroll
            for (int nt = 0; nt < NTILES; nt++) {
                int col = n0w + nt*8 + 2*t4;
                float2 bb = *(const float2*)&bias[col];
                #pragma unroll
                for (int half = 0; half < 2; half++) {
                    int row = g + half*8;
                    float2 o;
                    o.x = C[nt*4 + 2*half]     + bb.x;
                    o.y = C[nt*4 + 2*half + 1] + bb.y;
                    if (act) { o.x = gelu_f(o.x); o.y = gelu_f(o.y); }
                    if constexpr (SPLITOUT) {
                        float2 hi, lo;
                        hi.x = tf32f(o.x); hi.y = tf32f(o.y);
                        lo.x = tf32f(o.x - hi.x); lo.y = tf32f(o.y - hi.y);
                        *(float2*)&smOut[(size_t)row*opitch + col] = hi;
                        *(float2*)&smOut[(size_t)(row+16)*opitch + col] = lo;
                    } else {
                        *(float2*)&smOut[(size_t)row*opitch + col] = o;
                    }
                }
            }
        }
    }
}

__global__ void __launch_bounds__(NT, 3) fused_kernel(
    const float* __restrict__ x_enc, const float* __restrict__ eps,
    const float* __restrict__ p_aw, const float* __restrict__ p_ab,
    const float* __restrict__ b_sc,
    const float* __restrict__ b_r1, const float* __restrict__ b_r2,
    const float* __restrict__ b_r3,
    const float* __restrict__ flow_w, const float* __restrict__ flow_b,
    float* __restrict__ out)
{
    extern __shared__ float smn[];
    float* sA    = smn + P_A;       // xn pitch 340 / WT alias / inp2 / r2chunk2 / recon
    float* sINP  = smn + P_A;       // split: hi rows 0-15, lo rows 16-31, pitch 196
    float* sWT   = smn + P_A;       // gemm_s tiles (aliases dead xn)
    float* sPB   = smn + P_PB;
    float* sMean = smn + P_MEAN;
    float* sStd  = smn + P_STD;
    float* sScale= smn + P_SCALE;
    float* sB    = smn + P_B;       // mu/lv rows 0-15; hbuf rows 16-31; later r1out2
    float* hbuf  = sB + 16*PITCH_B;

    int tid = threadIdx.x;
    int n0 = blockIdx.x * ROWS;
    float aw = p_aw[0], ab = p_ab[0];
    int warp = tid >> 5, lane = tid & 31;
    float acc[8];

    // ---- 1. load x (pitch 340) ----
    for (int t = tid; t < ROWS*L; t += NT) {
        int r = t & 15, l = t >> 4;
        int n = n0 + r;
        int b = n / 7, c = n - b*7;
        sA[r*XP + l] = x_enc[(b*L + l)*7 + c];
    }
    __syncthreads();

    // ---- 2. per-row mean/std ----
    #pragma unroll
    for (int rr = 0; rr < 2; rr++) {
        int r = warp*2 + rr;
        const float* row = sA + r*XP;
        float s = 0.f, sq = 0.f;
        for (int l2 = lane; l2 < L; l2 += 32) { float v = row[l2]; s += v; sq += v*v; }
        #pragma unroll
        for (int o = 16; o > 0; o >>= 1) {
            s  += __shfl_xor_sync(0xffffffffu, s, o);
            sq += __shfl_xor_sync(0xffffffffu, sq, o);
        }
        if (lane == 0) {
            float mean = s * (1.f/336.f);
            float var = sq * (1.f/336.f) - mean*mean;
            float sd = sqrtf(var + 1e-5f);
            sMean[r] = mean; sStd[r] = sd; sScale[r] = aw / sd;
        }
    }
    __syncthreads();

    // ---- 3. normalize ----
    for (int t = tid; t < ROWS*L; t += NT) {
        int r = t / L, l = t - r*L;
        sA[r*XP + l] = (sA[r*XP + l] - sMean[r]) * sScale[r] + ab;
    }
    __syncthreads();

    // ---- 4. pbar ----
    {
        int r = tid >> 4, j = tid & 15;
        float s = 0.f;
        #pragma unroll
        for (int pp = 0; pp < 41; pp++) s += sA[r*XP + pp*8 + j];
        sPB[r*16 + j] = s * (1.f/41.f);
    }
    // (entry barrier of shortcut mma orders pbar/xn)

    // ---- 5. shortcut (3xTF32 mma, runtime A-split from xn) -> gmem scratch ----
    {
        float Cs[8];
        gemm_mma_reg<2,0,0>(sA, XP, 336, g_pk0, b_sc,
                            g_short + (size_t)n0*96, 96, 0, Cs, 1, 1, 6);
    }
    // (shortcut fin barrier: all xn reads retired -> WT alias safe)

    // ---- 6. h (FFMA exact) -> hbuf fp32 ----
    gemm_s(sPB, 16, 16, g_Wct, g_bc, hbuf, PITCH_B, sWT, acc);
    // ---- 7. [mu|lv] (FFMA exact, reads hbuf) -> sB rows 0-15 ----
    gemm_s(hbuf, PITCH_B, 128, g_Wmlt, g_bml, sB, PITCH_B, sWT, acc);
    __syncthreads();

    // ---- 8a. split h into inp2 cols 64..191 (WT now dead) ----
    for (int t = tid; t < ROWS*128; t += NT) {
        int r = t >> 7, m = t & 127;
        float h = hbuf[r*PITCH_B + m];
        float hi = tf32f(h);
        sINP[r*PITCH_INP + 64 + m] = hi;
        sINP[(r+16)*PITCH_INP + 64 + m] = tf32f(h - hi);
    }

    // ---- 8b+9. reparam + flows (FP64, bit-identical); write z split into inp2 ----
    #pragma unroll
    for (int rr = 0; rr < 2; rr++) {
        int r = warp + rr*8;
        int n = n0 + r;
        float mu0 = sB[r*PITCH_B + lane];
        float mu1 = sB[r*PITCH_B + 32 + lane];
        float lv0 = sB[r*PITCH_B + 64 + lane];
        float lv1 = sB[r*PITCH_B + 96 + lane];
        out[OFF_MU + n*64 + lane]      = mu0;
        out[OFF_MU + n*64 + 32 + lane] = mu1;
        out[OFF_LV + n*64 + lane]      = lv0;
        out[OFF_LV + n*64 + 32 + lane] = lv1;
        double z0 = (double)mu0 + (double)eps[n*64 + lane]      * exp(0.5 * (double)lv0);
        double z1 = (double)mu1 + (double)eps[n*64 + 32 + lane] * exp(0.5 * (double)lv1);
        double ld = 0.0;
        #pragma unroll
        for (int i = 0; i < 8; i++) {
            double w0 = (double)flow_w[i*64 + lane];
            double w1 = (double)flow_w[i*64 + 32 + lane];
            double dot = z0*w0 + z1*w1;
            #pragma unroll
            for (int o = 16; o > 0; o >>= 1) dot += __shfl_xor_sync(0xffffffffu, dot, o);
            double th = tanh(dot + (double)flow_b[i]);
            z0 += th * g_uhat[i*64 + lane];
            z1 += th * g_uhat[i*64 + 32 + lane];
            ld += log(fabs(1.0 + (1.0 - th*th) * g_cflow[i]) + 1e-6);
        }
        float z0f = (float)z0, z1f = (float)z1;
        float h0 = tf32f(z0f), h1 = tf32f(z1f);
        sINP[r*PITCH_INP + lane]              = h0;
        sINP[(r+16)*PITCH_INP + lane]         = tf32f(z0f - h0);
        sINP[r*PITCH_INP + 32 + lane]         = h1;
        sINP[(r+16)*PITCH_INP + 32 + lane]    = tf32f(z1f - h1);
        if (lane == 0) out[OFF_LD + n] = (float)ld;
    }
    // (r1 entry barrier orders h-split + flow writes)

    // ---- 10. r1 (mma, SPLITA, split-out) -> sB (r1out2) ----
    {
        float C1[16];
        gemm_mma_reg<4,1,1>(sINP, PITCH_INP, 192, g_pk1, b_r1, sB, PITCH_B, 1, C1, 1, 1, 8);
    }
    // ---- 11+12. r2 (4 chunks of 128, mma) fused with r3 accumulation ----
    {
        float C3[8];
        #pragma unroll
        for (int c = 0; c < 4; c++) {
            float C2[8];
            gemm_mma_reg<2,1,1>(sB, PITCH_B, 256, g_pk2 + (size_t)c*32*8*256, b_r2 + 128*c,
                                sA, 132, 1, C2, 1, 1, 8);
            gemm_mma_reg<2,1,0>(sA, 132, 128, g_pk3 + (size_t)c*16*8*256, b_r3,
                                sA, 100, 0, C3, c == 0, c == 3, 6);
        }
    }
    __syncthreads();

    // ---- 13. denorm + scatter (recon in sA pitch 100) ----
    float inv_aw = 1.f / (aw + 1e-10f);
    for (int t = tid; t < ROWS*96; t += NT) {
        int r = t & 15, pcol = t >> 4;
        int n = n0 + r;
        float v = sA[r*100 + pcol] + g_short[(size_t)n*96 + pcol];
        float den = fmaf((v - ab) * inv_aw, sStd[r], sMean[r]);
        int b = n/7, c = n - b*7;
        out[(b*96 + pcol)*7 + c] = den;
    }
}

extern "C" void kernel_launch(void* const* d_in, const int* in_sizes, int n_in,
                              void* d_out, int out_size) {
    const float* x_enc  = (const float*)d_in[0];
    const float* eps    = (const float*)d_in[1];
    const float* aw     = (const float*)d_in[2];
    const float* ab     = (const float*)d_in[3];
    const float* W_sc   = (const float*)d_in[4];
    const float* b_sc   = (const float*)d_in[5];
    const float* W_ts   = (const float*)d_in[6];
    const float* b_ts   = (const float*)d_in[7];
    const float* W_fu   = (const float*)d_in[8];
    const float* b_fu   = (const float*)d_in[9];
    const float* W_mu   = (const float*)d_in[10];
    const float* b_mu   = (const float*)d_in[11];
    const float* W_lv   = (const float*)d_in[12];
    const float* b_lv   = (const float*)d_in[13];
    const float* flow_u = (const float*)d_in[14];
    const float* flow_w = (const float*)d_in[15];
    const float* flow_b = (const float*)d_in[16];
    const float* W_r1   = (const float*)d_in[17];
    const float* b_r1   = (const float*)d_in[18];
    const float* W_r2   = (const float*)d_in[19];
    const float* b_r2   = (const float*)d_in[20];
    const float* W_r3   = (const float*)d_in[21];
    const float* b_r3   = (const float*)d_in[22];
    float* out = (float*)d_out;

    cudaFuncSetAttribute(fused_kernel, cudaFuncAttributeMaxDynamicSharedMemorySize, SMEM_BYTES);

    prep_kernel<<<128, 256>>>(W_sc, W_mu, b_mu, W_lv, b_lv, W_r3,
                              W_fu, b_fu, W_ts, b_ts, flow_u, flow_w, W_r1, W_r2);
    fused_kernel<<<448, NT, SMEM_BYTES>>>(x_enc, eps, aw, ab, b_sc,
                                          b_r1, b_r2, b_r3,
                                          flow_w, flow_b, out);
}

// round 16
// speedup vs baseline: 1.4062x; 1.0225x over previous
#include <cuda_runtime.h>
#include <math.h>
#include <stdint.h>

#define NT 256
#define ROWS 16
#define L 336
#define XP 340           // xn pitch (bank-clean for mma A loads: 340 % 32 = 20)
#define OFF_MU (1024*96*7)
#define OFF_LV (OFF_MU + 7168*64)
#define OFF_LD (OFF_LV + 7168*64)

// smem pool (floats)
#define P_A     0
#define P_PB    6272
#define P_MEAN  6528
#define P_STD   6544
#define P_SCALE 6560
#define P_B     6576     // [mu|lv] rows 0-15 pitch 260; hbuf rows 16-31; later r1out2 [32][260]
#define SMEM_FLOATS 14896
#define SMEM_BYTES (SMEM_FLOATS*4)

#define PITCH_INP 196
#define PITCH_B   260

// FFMA-path weights, k-major [k][m]
__device__ __align__(16) float g_Wmlt[128*128];   // [mu|lv]
__device__ __align__(16) float g_bml[128];
__device__ __align__(16) float g_Wct[16*128];
__device__ __align__(16) float g_bc[128];
// mma-path lane-packed pre-split tf32 frags: [tile][warp][ntile][lane][4]
__device__ __align__(16) float g_pk0[42*8*256];     // shortcut: K=336, M=128(96 pad), NTILES=2
__device__ __align__(16) float g_pk1[24*8*512];     // r1: K=192, M=256, NTILES=4
__device__ __align__(16) float g_pk2[4*32*8*256];   // r2: [ch(4)] K=256, M=128/ch, NTILES=2
__device__ __align__(16) float g_pk3[4*16*8*256];   // r3: [kq(4)] K=128/q, M=128(96 pad), NTILES=2
__device__ double g_uhat[8*64];
__device__ double g_cflow[8];
__device__ __align__(16) float g_short[7168*96];

__device__ __forceinline__ uint32_t f2tf(float x) {
    uint32_t r; asm("cvt.rna.tf32.f32 %0, %1;" : "=r"(r) : "f"(x)); return r;
}
__device__ __forceinline__ float tf32f(float x) {
    return __uint_as_float(f2tf(x));
}
__device__ __forceinline__ float split_val(float w, int plane) {
    float hi = tf32f(w);
    return plane ? tf32f(w - hi) : hi;
}

__global__ void prep_kernel(const float* __restrict__ W_sc,
                            const float* __restrict__ W_mu, const float* __restrict__ b_mu,
                            const float* __restrict__ W_lv, const float* __restrict__ b_lv,
                            const float* __restrict__ W_r3,
                            const float* __restrict__ W_fu, const float* __restrict__ b_fu,
                            const float* __restrict__ W_ts, const float* __restrict__ b_ts,
                            const float* __restrict__ flow_u, const float* __restrict__ flow_w,
                            const float* __restrict__ W_r1, const float* __restrict__ W_r2)
{
    int idx = blockIdx.x * blockDim.x + threadIdx.x;
    int stride = gridDim.x * blockDim.x;
    const int S0 = 128*128;              // Wmlt
    const int S1 = S0 + 128;             // bml
    const int S2 = S1 + 16*128;          // Wct
    const int S3 = S2 + 128;             // bc
    const int S4 = S3 + 42*8*256;        // pk0
    const int S5 = S4 + 24*8*512;        // pk1
    const int S6 = S5 + 4*32*8*256;      // pk2
    const int S7 = S6 + 4*16*8*256;      // pk3
    const int S8 = S7 + 8;               // flows
    for (int i = idx; i < S8; i += stride) {
        if (i < S0) {
            int k = i >> 7, m = i & 127;
            g_Wmlt[i] = (m < 64) ? W_mu[m*128 + k] : W_lv[(m-64)*128 + k];
        } else if (i < S1) {
            int j = i - S0;
            g_bml[j] = (j < 64) ? b_mu[j] : b_lv[j-64];
        } else if (i < S2) {
            int j = i - S1;
            int l = j >> 7, h = j & 127;
            float s = 0.f;
            for (int d = 0; d < 128; d++) s += W_fu[h*256 + d] * W_ts[d*16 + l];
            g_Wct[j] = s;
        } else if (i < S3) {
            int h = i - S2;
            float s = 0.f;
            for (int d = 0; d < 128; d++) s += W_fu[h*256 + d] * b_ts[d];
            g_bc[h] = s + b_fu[h];
        } else if (i < S4) {
            int j = i - S3;           // pk0: [t(42)][w(8)][c(1b)][l(32)][v(4)]
            int v = j & 3, l = (j >> 2) & 31, c = (j >> 7) & 1, w = (j >> 8) & 7, t = j >> 11;
            int g = l >> 2, t4 = l & 3;
            int m = w*16 + c*8 + g;
            int k = t*8 + t4 + (v & 1)*4;
            float wv = (m < 96) ? W_sc[m*336 + k] : 0.f;
            g_pk0[j] = split_val(wv, v >> 1);
        } else if (i < S5) {
            int j = i - S4;           // pk1: [t(24)][w(8)][c(2b)][l(32)][v(4)]
            int v = j & 3, l = (j >> 2) & 31, c = (j >> 7) & 3, w = (j >> 9) & 7, t = j >> 12;
            int g = l >> 2, t4 = l & 3;
            int m = w*32 + c*8 + g;
            int k = t*8 + t4 + (v & 1)*4;
            g_pk1[j] = split_val(W_r1[m*192 + k], v >> 1);
        } else if (i < S6) {
            int j = i - S5;           // pk2: [ch(2b)][t(32)][w(8)][c(1b)][l(32)][v(4)]
            int v = j & 3, l = (j >> 2) & 31, c = (j >> 7) & 1, w = (j >> 8) & 7, t = (j >> 11) & 31, ch = j >> 16;
            int g = l >> 2, t4 = l & 3;
            int m = ch*128 + w*16 + c*8 + g;
            int k = t*8 + t4 + (v & 1)*4;
            g_pk2[j] = split_val(W_r2[m*256 + k], v >> 1);
        } else if (i < S7) {
            int j = i - S6;           // pk3: [kq(2b)][t(16)][w(8)][c(1b)][l(32)][v(4)]
            int v = j & 3, l = (j >> 2) & 31, c = (j >> 7) & 1, w = (j >> 8) & 7, t = (j >> 11) & 15, kq = j >> 15;
            int g = l >> 2, t4 = l & 3;
            int m = w*16 + c*8 + g;
            int k = kq*128 + t*8 + t4 + (v & 1)*4;
            float wv = (m < 96) ? W_r3[m*512 + k] : 0.f;
            g_pk3[j] = split_val(wv, v >> 1);
        } else {
            int fi = i - S7;
            double s = 0.0, wsq = 0.0;
            for (int d = 0; d < 64; d++) {
                double u = (double)flow_u[fi*64+d], w = (double)flow_w[fi*64+d];
                s += u*w; wsq += w*w;
            }
            double sp = (s > 0.0) ? s + log1p(exp(-s)) : log1p(exp(s));
            double m = -1.0 + sp;
            double coef = m / (wsq + 1e-6);
            for (int d = 0; d < 64; d++)
                g_uhat[fi*64+d] = (double)flow_u[fi*64+d] + coef*(double)flow_w[fi*64+d];
            g_cflow[fi] = s + coef * wsq;
        }
    }
}

__device__ __forceinline__ float gelu_f(float x) {
    return 0.5f * x * (1.f + erff(x * 0.70710678118654752f));
}
__device__ __forceinline__ uint32_t smem_u32(const void* p) {
    return (uint32_t)__cvta_generic_to_shared(p);
}
#define CP_ASYNC16(d, s) asm volatile("cp.async.ca.shared.global [%0], [%1], 16;\n" :: "r"(d), "l"(s))
#define CP_COMMIT()      asm volatile("cp.async.commit_group;\n" ::: "memory")
#define CP_WAIT0()       asm volatile("cp.async.wait_group 0;\n" ::: "memory")

#define MMA_TF32(c, a0,a1,a2,a3, b0,b1) \
    asm volatile("mma.sync.aligned.m16n8k8.row.col.f32.tf32.tf32.f32 " \
        "{%0,%1,%2,%3}, {%4,%5,%6,%7}, {%8,%9}, {%0,%1,%2,%3};" \
        : "+f"((c)[0]), "+f"((c)[1]), "+f"((c)[2]), "+f"((c)[3]) \
        : "r"(a0), "r"(a1), "r"(a2), "r"(a3), "r"(b0), "r"(b1))

// ---------------- FFMA fp32 GEMM (bit-exact; h and mu/lv only), KT=16 ----------------
__device__ __forceinline__ void gemm_s(
    const float* smIn, int pitch, int K,
    const float* __restrict__ Wk, const float* __restrict__ bias,
    float* smOut, int opitch, float* Wt, float* acc)
{
    const int tid = threadIdx.x;
    const int rg = tid >> 6;
    const int mloc = (tid & 63) << 1;
    const int srow = tid >> 5;
    const int scol = (tid & 31) << 2;
    const float* in0 = smIn + rg*4*pitch;
    const int T = K >> 4;
    {
        #pragma unroll
        for (int s2 = 0; s2 < 2; s2++) {
            CP_ASYNC16(smem_u32(Wt + (srow + 8*s2)*132 + scol), Wk + (size_t)(srow + 8*s2)*128 + scol);
        }
        CP_COMMIT();
    }
    #pragma unroll
    for (int i = 0; i < 8; i++) acc[i] = 0.f;
    int buf = 0;
    for (int t = 0; t < T; t++) {
        CP_WAIT0();
        __syncthreads();
        if (t + 1 < T) {
            const float* g = Wk + (size_t)((t+1)*16)*128;
            float* Wd = Wt + (buf^1)*2112;
            #pragma unroll
            for (int s2 = 0; s2 < 2; s2++) {
                CP_ASYNC16(smem_u32(Wd + (srow + 8*s2)*132 + scol), g + (size_t)(srow + 8*s2)*128 + scol);
            }
            CP_COMMIT();
        }
        const float* W = Wt + buf*2112;
        const float* i0 = in0 + t*16;
        #pragma unroll
        for (int kk = 0; kk < 16; kk += 2) {
            float2 w0 = *(const float2*)&W[kk*132 + mloc];
            float2 w1 = *(const float2*)&W[(kk+1)*132 + mloc];
            float2 x0 = *(const float2*)(i0 + kk);
            float2 x1 = *(const float2*)(i0 + pitch + kk);
            float2 x2 = *(const float2*)(i0 + 2*pitch + kk);
            float2 x3 = *(const float2*)(i0 + 3*pitch + kk);
            acc[0] = fmaf(x0.x, w0.x, acc[0]); acc[0] = fmaf(x0.y, w1.x, acc[0]);
            acc[1] = fmaf(x0.x, w0.y, acc[1]); acc[1] = fmaf(x0.y, w1.y, acc[1]);
            acc[2] = fmaf(x1.x, w0.x, acc[2]); acc[2] = fmaf(x1.y, w1.x, acc[2]);
            acc[3] = fmaf(x1.x, w0.y, acc[3]); acc[3] = fmaf(x1.y, w1.y, acc[3]);
            acc[4] = fmaf(x2.x, w0.x, acc[4]); acc[4] = fmaf(x2.y, w1.x, acc[4]);
            acc[5] = fmaf(x2.x, w0.y, acc[5]); acc[5] = fmaf(x2.y, w1.y, acc[5]);
            acc[6] = fmaf(x3.x, w0.x, acc[6]); acc[6] = fmaf(x3.y, w1.x, acc[6]);
            acc[7] = fmaf(x3.x, w0.y, acc[7]); acc[7] = fmaf(x3.y, w1.y, acc[7]);
        }
        buf ^= 1;
    }
    __syncthreads();
    {
        float b0 = bias[mloc], b1 = bias[mloc+1];
        int r0 = rg*4;
        #pragma unroll
        for (int r = 0; r < 4; r++) {
            float2 o;
            o.x = acc[2*r]   + b0;
            o.y = acc[2*r+1] + b1;
            *(float2*)&smOut[(size_t)(r0+r)*opitch + mloc] = o;
        }
    }
}

// ---------------- 3xTF32 mma GEMM, register-direct weights, DEPTH-deep prefetch ----------------
// SPLITA: A planes pre-split in smem (hi rows 0-15, lo rows 16-31); else runtime split.
// SPLITOUT: store tf32 hi/lo planes; else plain fp32. Requires K/8 % DEPTH == 0.
template<int NTILES, int SPLITA, int SPLITOUT, int DEPTH>
__device__ __forceinline__ void gemm_mma_reg(
    const float* smIn, int pitch, int K,
    const float* __restrict__ pk,
    const float* __restrict__ bias,
    float* smOut, int opitch, int act,
    float* C, int init, int fin, int nws)
{
    constexpr int TBV = NTILES*32;
    const int tid = threadIdx.x;
    const int lane = tid & 31;
    const int warp = tid >> 5;
    const int g = lane >> 2, t4 = lane & 3;
    const int n0w = warp * (8*NTILES);
    const int T = K >> 3;
    const float4* pw = (const float4*)pk + (size_t)warp*TBV + lane;
    const int wstep = 8*TBV;

    __syncthreads();
    float4 q[DEPTH][NTILES];
    #pragma unroll
    for (int d = 0; d < DEPTH; d++) {
        const float4* p = pw + (size_t)d*wstep;
        #pragma unroll
        for (int c = 0; c < NTILES; c++) q[d][c] = __ldg(p + c*32);
    }
    if (init) {
        #pragma unroll
        for (int i = 0; i < 4*NTILES; i++) C[i] = 0.f;
    }

    auto mma_step = [&](int tt, float4* qv) {
        const float* ia = smIn + tt*8;
        uint32_t ah0, ah1, ah2, ah3, al0, al1, al2, al3;
        if constexpr (SPLITA) {
            ah0 = __float_as_uint(ia[g*pitch + t4]);
            ah1 = __float_as_uint(ia[(g+8)*pitch + t4]);
            ah2 = __float_as_uint(ia[g*pitch + t4 + 4]);
            ah3 = __float_as_uint(ia[(g+8)*pitch + t4 + 4]);
            al0 = __float_as_uint(ia[(g+16)*pitch + t4]);
            al1 = __float_as_uint(ia[(g+24)*pitch + t4]);
            al2 = __float_as_uint(ia[(g+16)*pitch + t4 + 4]);
            al3 = __float_as_uint(ia[(g+24)*pitch + t4 + 4]);
        } else {
            float ar0 = ia[g*pitch + t4];
            float ar1 = ia[(g+8)*pitch + t4];
            float ar2 = ia[g*pitch + t4 + 4];
            float ar3 = ia[(g+8)*pitch + t4 + 4];
            ah0 = f2tf(ar0); ah1 = f2tf(ar1); ah2 = f2tf(ar2); ah3 = f2tf(ar3);
            al0 = f2tf(ar0 - __uint_as_float(ah0));
            al1 = f2tf(ar1 - __uint_as_float(ah1));
            al2 = f2tf(ar2 - __uint_as_float(ah2));
            al3 = f2tf(ar3 - __uint_as_float(ah3));
        }
        #pragma unroll
        for (int nt = 0; nt < NTILES; nt++) {
            uint32_t bh0 = __float_as_uint(qv[nt].x);
            uint32_t bh1 = __float_as_uint(qv[nt].y);
            uint32_t bl0 = __float_as_uint(qv[nt].z);
            uint32_t bl1 = __float_as_uint(qv[nt].w);
            float* c = C + nt*4;
            MMA_TF32(c, ah0, ah1, ah2, ah3, bh0, bh1);
            MMA_TF32(c, ah0, ah1, ah2, ah3, bl0, bl1);
            MMA_TF32(c, al0, al1, al2, al3, bh0, bh1);
        }
    };

    for (int t = 0; t < T; t += DEPTH) {
        bool more = (t + DEPTH < T);
        #pragma unroll
        for (int d = 0; d < DEPTH; d++) {
            mma_step(t + d, q[d]);
            if (more) {
                const float4* p = pw + (size_t)(t + d + DEPTH)*wstep;
                #pragma unroll
                for (int c = 0; c < NTILES; c++) q[d][c] = __ldg(p + c*32);
            }
        }
    }

    if (fin) {
        __syncthreads();
        if (warp < nws) {
            #pragma unroll
            for (int nt = 0; nt < NTILES; nt++) {
                int col = n0w + nt*8 + 2*t4;
                float2 bb = *(const float2*)&bias[col];
                #pragma unroll
                for (int half = 0; half < 2; half++) {
                    int row = g + half*8;
                    float2 o;
                    o.x = C[nt*4 + 2*half]     + bb.x;
                    o.y = C[nt*4 + 2*half + 1] + bb.y;
                    if (act) { o.x = gelu_f(o.x); o.y = gelu_f(o.y); }
                    if constexpr (SPLITOUT) {
                        float2 hi, lo;
                        hi.x = tf32f(o.x); hi.y = tf32f(o.y);
                        lo.x = tf32f(o.x - hi.x); lo.y = tf32f(o.y - hi.y);
                        *(float2*)&smOut[(size_t)row*opitch + col] = hi;
                        *(float2*)&smOut[(size_t)(row+16)*opitch + col] = lo;
                    } else {
                        *(float2*)&smOut[(size_t)row*opitch + col] = o;
                    }
                }
            }
        }
    }
}

__global__ void __launch_bounds__(NT, 3) fused_kernel(
    const float* __restrict__ x_enc, const float* __restrict__ eps,
    const float* __restrict__ p_aw, const float* __restrict__ p_ab,
    const float* __restrict__ b_sc,
    const float* __restrict__ b_r1, const float* __restrict__ b_r2,
    const float* __restrict__ b_r3,
    const float* __restrict__ flow_w, const float* __restrict__ flow_b,
    float* __restrict__ out)
{
    extern __shared__ float smn[];
    float* sA    = smn + P_A;       // xn pitch 340 / WT alias / inp2 / r2chunk2 / recon
    float* sINP  = smn + P_A;       // split: hi rows 0-15, lo rows 16-31, pitch 196
    float* sWT   = smn + P_A;       // gemm_s tiles (aliases dead xn)
    float* sPB   = smn + P_PB;
    float* sMean = smn + P_MEAN;
    float* sStd  = smn + P_STD;
    float* sScale= smn + P_SCALE;
    float* sB    = smn + P_B;       // mu/lv rows 0-15; hbuf rows 16-31; later r1out2
    float* hbuf  = sB + 16*PITCH_B;

    int tid = threadIdx.x;
    int n0 = blockIdx.x * ROWS;
    float aw = p_aw[0], ab = p_ab[0];
    int warp = tid >> 5, lane = tid & 31;
    float acc[8];

    // ---- 1. load x (pitch 340) ----
    for (int t = tid; t < ROWS*L; t += NT) {
        int r = t & 15, l = t >> 4;
        int n = n0 + r;
        int b = n / 7, c = n - b*7;
        sA[r*XP + l] = x_enc[(b*L + l)*7 + c];
    }
    __syncthreads();

    // ---- 2. per-row mean/std ----
    #pragma unroll
    for (int rr = 0; rr < 2; rr++) {
        int r = warp*2 + rr;
        const float* row = sA + r*XP;
        float s = 0.f, sq = 0.f;
        for (int l2 = lane; l2 < L; l2 += 32) { float v = row[l2]; s += v; sq += v*v; }
        #pragma unroll
        for (int o = 16; o > 0; o >>= 1) {
            s  += __shfl_xor_sync(0xffffffffu, s, o);
            sq += __shfl_xor_sync(0xffffffffu, sq, o);
        }
        if (lane == 0) {
            float mean = s * (1.f/336.f);
            float var = sq * (1.f/336.f) - mean*mean;
            float sd = sqrtf(var + 1e-5f);
            sMean[r] = mean; sStd[r] = sd; sScale[r] = aw / sd;
        }
    }
    __syncthreads();

    // ---- 3. normalize ----
    for (int t = tid; t < ROWS*L; t += NT) {
        int r = t / L, l = t - r*L;
        sA[r*XP + l] = (sA[r*XP + l] - sMean[r]) * sScale[r] + ab;
    }
    __syncthreads();

    // ---- 4. pbar ----
    {
        int r = tid >> 4, j = tid & 15;
        float s = 0.f;
        #pragma unroll
        for (int pp = 0; pp < 41; pp++) s += sA[r*XP + pp*8 + j];
        sPB[r*16 + j] = s * (1.f/41.f);
    }
    // (entry barrier of shortcut mma orders pbar/xn)

    // ---- 5. shortcut (mma, runtime A-split from xn, DEPTH=3) -> gmem scratch ----
    {
        float Cs[8];
        gemm_mma_reg<2,0,0,3>(sA, XP, 336, g_pk0, b_sc,
                              g_short + (size_t)n0*96, 96, 0, Cs, 1, 1, 6);
    }
    // (shortcut fin barrier: all xn reads retired -> WT alias safe)

    // ---- 6. h (FFMA exact) -> hbuf fp32 ----
    gemm_s(sPB, 16, 16, g_Wct, g_bc, hbuf, PITCH_B, sWT, acc);
    // ---- 7. [mu|lv] (FFMA exact, reads hbuf) -> sB rows 0-15 ----
    gemm_s(hbuf, PITCH_B, 128, g_Wmlt, g_bml, sB, PITCH_B, sWT, acc);
    __syncthreads();

    // ---- 8a. split h into inp2 cols 64..191 (WT now dead) ----
    for (int t = tid; t < ROWS*128; t += NT) {
        int r = t >> 7, m = t & 127;
        float h = hbuf[r*PITCH_B + m];
        float hi = tf32f(h);
        sINP[r*PITCH_INP + 64 + m] = hi;
        sINP[(r+16)*PITCH_INP + 64 + m] = tf32f(h - hi);
    }

    // ---- 8b+9. reparam + flows (FP64, bit-identical); write z split into inp2 ----
    #pragma unroll
    for (int rr = 0; rr < 2; rr++) {
        int r = warp + rr*8;
        int n = n0 + r;
        float mu0 = sB[r*PITCH_B + lane];
        float mu1 = sB[r*PITCH_B + 32 + lane];
        float lv0 = sB[r*PITCH_B + 64 + lane];
        float lv1 = sB[r*PITCH_B + 96 + lane];
        out[OFF_MU + n*64 + lane]      = mu0;
        out[OFF_MU + n*64 + 32 + lane] = mu1;
        out[OFF_LV + n*64 + lane]      = lv0;
        out[OFF_LV + n*64 + 32 + lane] = lv1;
        double z0 = (double)mu0 + (double)eps[n*64 + lane]      * exp(0.5 * (double)lv0);
        double z1 = (double)mu1 + (double)eps[n*64 + 32 + lane] * exp(0.5 * (double)lv1);
        double ld = 0.0;
        #pragma unroll
        for (int i = 0; i < 8; i++) {
            double w0 = (double)flow_w[i*64 + lane];
            double w1 = (double)flow_w[i*64 + 32 + lane];
            double dot = z0*w0 + z1*w1;
            #pragma unroll
            for (int o = 16; o > 0; o >>= 1) dot += __shfl_xor_sync(0xffffffffu, dot, o);
            double th = tanh(dot + (double)flow_b[i]);
            z0 += th * g_uhat[i*64 + lane];
            z1 += th * g_uhat[i*64 + 32 + lane];
            ld += log(fabs(1.0 + (1.0 - th*th) * g_cflow[i]) + 1e-6);
        }
        float z0f = (float)z0, z1f = (float)z1;
        float h0 = tf32f(z0f), h1 = tf32f(z1f);
        sINP[r*PITCH_INP + lane]              = h0;
        sINP[(r+16)*PITCH_INP + lane]         = tf32f(z0f - h0);
        sINP[r*PITCH_INP + 32 + lane]         = h1;
        sINP[(r+16)*PITCH_INP + 32 + lane]    = tf32f(z1f - h1);
        if (lane == 0) out[OFF_LD + n] = (float)ld;
    }
    // (r1 entry barrier orders h-split + flow writes)

    // ---- 10. r1 (mma, SPLITA, split-out, DEPTH=2) -> sB (r1out2) ----
    {
        float C1[16];
        gemm_mma_reg<4,1,1,2>(sINP, PITCH_INP, 192, g_pk1, b_r1, sB, PITCH_B, 1, C1, 1, 1, 8);
    }
    // ---- 11+12. r2 (4 chunks of 128, mma DEPTH=4) fused with r3 (mma DEPTH=4) ----
    {
        float C3[8];
        #pragma unroll
        for (int c = 0; c < 4; c++) {
            float C2[8];
            gemm_mma_reg<2,1,1,4>(sB, PITCH_B, 256, g_pk2 + (size_t)c*32*8*256, b_r2 + 128*c,
                                  sA, 132, 1, C2, 1, 1, 8);
            gemm_mma_reg<2,1,0,4>(sA, 132, 128, g_pk3 + (size_t)c*16*8*256, b_r3,
                                  sA, 100, 0, C3, c == 0, c == 3, 6);
        }
    }
    __syncthreads();

    // ---- 13. denorm + scatter (recon in sA pitch 100) ----
    float inv_aw = 1.f / (aw + 1e-10f);
    for (int t = tid; t < ROWS*96; t += NT) {
        int r = t & 15, pcol = t >> 4;
        int n = n0 + r;
        float v = sA[r*100 + pcol] + g_short[(size_t)n*96 + pcol];
        float den = fmaf((v - ab) * inv_aw, sStd[r], sMean[r]);
        int b = n/7, c = n - b*7;
        out[(b*96 + pcol)*7 + c] = den;
    }
}

extern "C" void kernel_launch(void* const* d_in, const int* in_sizes, int n_in,
                              void* d_out, int out_size) {
    const float* x_enc  = (const float*)d_in[0];
    const float* eps    = (const float*)d_in[1];
    const float* aw     = (const float*)d_in[2];
    const float* ab     = (const float*)d_in[3];
    const float* W_sc   = (const float*)d_in[4];
    const float* b_sc   = (const float*)d_in[5];
    const float* W_ts   = (const float*)d_in[6];
    const float* b_ts   = (const float*)d_in[7];
    const float* W_fu   = (const float*)d_in[8];
    const float* b_fu   = (const float*)d_in[9];
    const float* W_mu   = (const float*)d_in[10];
    const float* b_mu   = (const float*)d_in[11];
    const float* W_lv   = (const float*)d_in[12];
    const float* b_lv   = (const float*)d_in[13];
    const float* flow_u = (const float*)d_in[14];
    const float* flow_w = (const float*)d_in[15];
    const float* flow_b = (const float*)d_in[16];
    const float* W_r1   = (const float*)d_in[17];
    const float* b_r1   = (const float*)d_in[18];
    const float* W_r2   = (const float*)d_in[19];
    const float* b_r2   = (const float*)d_in[20];
    const float* W_r3   = (const float*)d_in[21];
    const float* b_r3   = (const float*)d_in[22];
    float* out = (float*)d_out;

    cudaFuncSetAttribute(fused_kernel, cudaFuncAttributeMaxDynamicSharedMemorySize, SMEM_BYTES);

    prep_kernel<<<128, 256>>>(W_sc, W_mu, b_mu, W_lv, b_lv, W_r3,
                              W_fu, b_fu, W_ts, b_ts, flow_u, flow_w, W_r1, W_r2);
    fused_kernel<<<448, NT, SMEM_BYTES>>>(x_enc, eps, aw, ab, b_sc,
                                          b_r1, b_r2, b_r3,
                                          flow_w, flow_b, out);
}